// round 9
// baseline (speedup 1.0000x reference)
#include <cuda_runtime.h>
#include <math.h>
#include <stdint.h>

#define BATCH   8
#define CHN     512
#define NPOS    9216         // 96*96
#define IMGW    96
#define HEADS   4
#define HD      128
#define QUARTER 2304         // NPOS/4
#define KV_SPLIT 18
#define KV_CHUNK 512         // NPOS / KV_SPLIT

// ---------------- scratch (device globals; no allocation allowed) -------------
__device__ float g_q[BATCH * CHN * NPOS];                       // 151 MB
__device__ float g_k[BATCH * CHN * NPOS];                       // 151 MB
__device__ float g_S[BATCH * HEADS * CHN];
__device__ float g_kmean[BATCH * HEADS * HD];
__device__ float g_z[BATCH * HEADS * NPOS];
__device__ float g_kvp[BATCH * HEADS * KV_SPLIT * HD * HD];     // 37.7 MB
__device__ float g_kv[BATCH * HEADS * HD * HD];

__device__ __forceinline__ float elu1(float v) {
    return v > 0.f ? v + 1.f : expf(v);
}

// ---------------- packed f32x2 helpers (Blackwell sm_103a) --------------------
__device__ __forceinline__ unsigned long long pack2(float lo, float hi) {
    unsigned long long r;
    asm("mov.b64 %0, {%1, %2};" : "=l"(r) : "f"(lo), "f"(hi));
    return r;
}
__device__ __forceinline__ void unpack2(unsigned long long v, float& lo, float& hi) {
    asm("mov.b64 {%0, %1}, %2;" : "=f"(lo), "=f"(hi) : "l"(v));
}
// d = a * b + d  (two independent IEEE fp32 FMAs per issue slot)
__device__ __forceinline__ void ffma2(unsigned long long& d,
                                      unsigned long long a, unsigned long long b) {
    asm("fma.rn.f32x2 %0, %1, %2, %0;" : "+l"(d) : "l"(a), "l"(b));
}

// ============================================================================
// Kernel 1: per-batch GEMM  qk[b] (1024 x 9216) = W_qk (1024x512) @ x[b] (512x9216)
// fused bias + elu + 1.  Software-pipelined: register prefetch of tile t+1
// overlaps LDG latency with tile t's FFMA2 compute.
// ============================================================================
__global__ __launch_bounds__(256) void qk_gemm_kernel(const float* __restrict__ x,
                                                      const float* __restrict__ Wqk,
                                                      const float* __restrict__ bqk) {
    __shared__ float As[16][132];   // [k][m]
    __shared__ float Bs[16][128];   // [k][n]
    const int bN = blockIdx.x * 128;
    const int bM = blockIdx.y * 128;
    const int bb = blockIdx.z;
    const float* X = x + (size_t)bb * CHN * NPOS;

    const int tid = threadIdx.x;
    const int tx = tid & 15, ty = tid >> 4;

    // load-index precompute
    const int a_row0 = (tid) >> 2,        a_c40 = ((tid) & 3) * 4;
    const int a_row1 = (tid + 256) >> 2,  a_c41 = ((tid + 256) & 3) * 4;
    const int b_kk0  = (tid) >> 5,        b_c40 = ((tid) & 31) * 4;
    const int b_kk1  = (tid + 256) >> 5,  b_c41 = ((tid + 256) & 31) * 4;

    unsigned long long acc2[8][4];
#pragma unroll
    for (int i = 0; i < 8; i++)
#pragma unroll
        for (int j = 0; j < 4; j++) acc2[i][j] = 0ull;

    float4 pa0, pa1, pb0, pb1;
    // prefetch tile kt=0
    pa0 = *(const float4*)&Wqk[(size_t)(bM + a_row0) * CHN + 0 + a_c40];
    pa1 = *(const float4*)&Wqk[(size_t)(bM + a_row1) * CHN + 0 + a_c41];
    pb0 = *(const float4*)&X[(size_t)(0 + b_kk0) * NPOS + bN + b_c40];
    pb1 = *(const float4*)&X[(size_t)(0 + b_kk1) * NPOS + bN + b_c41];

    for (int kt = 0; kt < CHN; kt += 16) {
        // commit prefetched tile to smem
        As[a_c40 + 0][a_row0] = pa0.x;
        As[a_c40 + 1][a_row0] = pa0.y;
        As[a_c40 + 2][a_row0] = pa0.z;
        As[a_c40 + 3][a_row0] = pa0.w;
        As[a_c41 + 0][a_row1] = pa1.x;
        As[a_c41 + 1][a_row1] = pa1.y;
        As[a_c41 + 2][a_row1] = pa1.z;
        As[a_c41 + 3][a_row1] = pa1.w;
        *(float4*)&Bs[b_kk0][b_c40] = pb0;
        *(float4*)&Bs[b_kk1][b_c41] = pb1;
        __syncthreads();

        // prefetch next tile (overlaps with compute below)
        const int ktn = kt + 16;
        if (ktn < CHN) {
            pa0 = *(const float4*)&Wqk[(size_t)(bM + a_row0) * CHN + ktn + a_c40];
            pa1 = *(const float4*)&Wqk[(size_t)(bM + a_row1) * CHN + ktn + a_c41];
            pb0 = *(const float4*)&X[(size_t)(ktn + b_kk0) * NPOS + bN + b_c40];
            pb1 = *(const float4*)&X[(size_t)(ktn + b_kk1) * NPOS + bN + b_c41];
        }

#pragma unroll
        for (int kk = 0; kk < 16; kk++) {
            float a[8];
            *(float4*)&a[0]  = *(const float4*)&As[kk][ty * 4];
            *(float4*)&a[4]  = *(const float4*)&As[kk][64 + ty * 4];
            float4 b0 = *(const float4*)&Bs[kk][tx * 4];
            float4 b1 = *(const float4*)&Bs[kk][64 + tx * 4];
            unsigned long long bb4[4];
            bb4[0] = pack2(b0.x, b0.y);
            bb4[1] = pack2(b0.z, b0.w);
            bb4[2] = pack2(b1.x, b1.y);
            bb4[3] = pack2(b1.z, b1.w);
#pragma unroll
            for (int i = 0; i < 8; i++) {
                unsigned long long aa = pack2(a[i], a[i]);
                ffma2(acc2[i][0], aa, bb4[0]);
                ffma2(acc2[i][1], aa, bb4[1]);
                ffma2(acc2[i][2], aa, bb4[2]);
                ffma2(acc2[i][3], aa, bb4[3]);
            }
        }
        __syncthreads();
    }

    // epilogue: bias + elu + 1, route to q or k buffer (channels-first)
#pragma unroll
    for (int ih = 0; ih < 2; ih++) {
#pragma unroll
        for (int i2 = 0; i2 < 4; i2++) {
            int i = ih * 4 + i2;
            int row = bM + ih * 64 + ty * 4 + i2;
            float bvv = bqk[row];
            float* dst = (row < CHN)
                ? &g_q[((size_t)bb * CHN + row) * NPOS]
                : &g_k[((size_t)bb * CHN + (row - CHN)) * NPOS];
#pragma unroll
            for (int jh = 0; jh < 2; jh++) {
                int col = bN + jh * 64 + tx * 4;
                float lo0, hi0, lo1, hi1;
                unpack2(acc2[i][jh * 2 + 0], lo0, hi0);
                unpack2(acc2[i][jh * 2 + 1], lo1, hi1);
                float4 o;
                o.x = elu1(lo0 + bvv);
                o.y = elu1(hi0 + bvv);
                o.z = elu1(lo1 + bvv);
                o.w = elu1(hi1 + bvv);
                *(float4*)&dst[col] = o;
            }
        }
    }
}

// ============================================================================
// Kernel 2a: per-(b, channel) quarter-n sums of raw k
// ============================================================================
__global__ __launch_bounds__(256) void colsum_kernel() {
    const int c = blockIdx.x, bb = blockIdx.y;
    const float* src = &g_k[((size_t)bb * CHN + c) * NPOS];
    const int tid = threadIdx.x;
    const int q = tid >> 6, l = tid & 63;
    float s = 0.f;
#pragma unroll
    for (int i = 0; i < 36; i++) s += src[q * QUARTER + l + 64 * i];
    __shared__ float red[256];
    red[tid] = s;
    __syncthreads();
#pragma unroll
    for (int off = 32; off >= 1; off >>= 1) {
        if (l < off) red[tid] += red[tid + off];
        __syncthreads();
    }
    if (l == 0) g_S[((size_t)bb * HEADS + q) * CHN + c] = red[tid];
}

__global__ void kmean_kernel() {
    int idx = blockIdx.x * 256 + threadIdx.x;
    if (idx >= BATCH * HEADS * HD) return;
    int d  = idx & 127;
    int hh = (idx >> 7) & 3;
    int bb = idx >> 9;
    const float* S = &g_S[((size_t)bb * HEADS + hh) * CHN];
    g_kmean[idx] = (S[d] + S[128 + d] + S[256 + d] + S[384 + d]) * (1.f / NPOS);
}

// ============================================================================
// Kernel 3: z = 1 / (q_raw . k_mean + eps)
// ============================================================================
__global__ __launch_bounds__(256) void z_kernel() {
    const int chunk = blockIdx.x;
    const int hh = blockIdx.y, bb = blockIdx.z;
    const int tid = threadIdx.x;
    __shared__ float km[HD];
    if (tid < HD) km[tid] = g_kmean[((size_t)bb * HEADS + hh) * HD + tid];
    __syncthreads();
    const int rp = chunk * 256 + tid;
    const float* qbase = g_q + (size_t)bb * CHN * NPOS + (size_t)hh * QUARTER + rp;
    float a0 = 0.f, a1 = 0.f, a2 = 0.f, a3 = 0.f;
#pragma unroll 4
    for (int d = 0; d < HD; d++) {
        float kmv = km[d];
        a0 += qbase[(size_t)(d)       * NPOS] * kmv;
        a1 += qbase[(size_t)(128 + d) * NPOS] * kmv;
        a2 += qbase[(size_t)(256 + d) * NPOS] * kmv;
        a3 += qbase[(size_t)(384 + d) * NPOS] * kmv;
    }
    float* zb = &g_z[((size_t)bb * HEADS + hh) * NPOS + 4 * rp];
    zb[0] = 1.f / (a0 + 1e-6f);
    zb[1] = 1.f / (a1 + 1e-6f);
    zb[2] = 1.f / (a2 + 1e-6f);
    zb[3] = 1.f / (a3 + 1e-6f);
}

// ============================================================================
// Kernel 4: in-place RoPE; angle indexed by COLUMN (pos % 96) per reference broadcast
// ============================================================================
__global__ __launch_bounds__(256) void rope_kernel() {
    const int pos = blockIdx.x * 256 + threadIdx.x;
    const int p = blockIdx.y;
    const int zb = blockIdx.z;
    const int bb = zb >> 1;
    float* buf = (zb & 1) ? g_k : g_q;
    const int col = pos % IMGW;
    float theta = expf((float)p * (-9.210340371976184f / 256.f));
    float ang = (float)col * theta;
    float s, c;
    sincosf(ang, &s, &c);
    size_t base = ((size_t)bb * CHN + 2 * p) * NPOS + pos;
    float re = buf[base];
    float im = buf[base + NPOS];
    buf[base]        = c * re - s * im;
    buf[base + NPOS] = s * re + c * im;
}

// ============================================================================
// Kernel 5: kv partials (split-K, register-prefetch pipelined, ffma2)
// ============================================================================
__global__ __launch_bounds__(256) void kv_kernel(const float* __restrict__ x) {
    const int chunk = blockIdx.x;
    const int hh = blockIdx.y, bb = blockIdx.z;
    __shared__ float As[32][132];
    __shared__ float Bs[32][132];
    const int tid = threadIdx.x;
    const int tx = tid & 15, ty = tid >> 4;

    unsigned long long acc2[8][4];
#pragma unroll
    for (int i = 0; i < 8; i++)
#pragma unroll
        for (int j = 0; j < 4; j++) acc2[i][j] = 0ull;

    const float* kr = &g_k[((size_t)bb * CHN + 128 * hh) * NPOS];

    const int a_g = tid & 7;
    const int a_db = tid >> 3;
    const int b_rg = tid & 1;
    const int b_j  = (tid >> 1) & 3;
    const int b_eb = tid >> 3;

    float4 pA[4], pB[4];
    // prefetch t = 0
    {
        const int m0 = chunk * KV_CHUNK;
        const int posb = hh * QUARTER + (m0 >> 2);
#pragma unroll
        for (int r = 0; r < 4; r++) {
            pA[r] = *(const float4*)&kr[(size_t)(a_db + 32 * r) * NPOS + m0 + a_g * 4];
            pB[r] = *(const float4*)(x + ((size_t)bb * CHN + 128 * b_j + b_eb + 32 * r) * NPOS + posb + b_rg * 4);
        }
    }

    for (int t = 0; t < KV_CHUNK / 32; t++) {
        // commit prefetched tile
#pragma unroll
        for (int r = 0; r < 4; r++) {
            int d = a_db + 32 * r;
            As[a_g * 4 + 0][d] = pA[r].x;
            As[a_g * 4 + 1][d] = pA[r].y;
            As[a_g * 4 + 2][d] = pA[r].z;
            As[a_g * 4 + 3][d] = pA[r].w;
            int e = b_eb + 32 * r;
            Bs[(b_rg * 4 + 0) * 4 + b_j][e] = pB[r].x;
            Bs[(b_rg * 4 + 1) * 4 + b_j][e] = pB[r].y;
            Bs[(b_rg * 4 + 2) * 4 + b_j][e] = pB[r].z;
            Bs[(b_rg * 4 + 3) * 4 + b_j][e] = pB[r].w;
        }
        __syncthreads();

        // prefetch next tile
        if (t + 1 < KV_CHUNK / 32) {
            const int m0n = chunk * KV_CHUNK + (t + 1) * 32;
            const int posbn = hh * QUARTER + (m0n >> 2);
#pragma unroll
            for (int r = 0; r < 4; r++) {
                pA[r] = *(const float4*)&kr[(size_t)(a_db + 32 * r) * NPOS + m0n + a_g * 4];
                pB[r] = *(const float4*)(x + ((size_t)bb * CHN + 128 * b_j + b_eb + 32 * r) * NPOS + posbn + b_rg * 4);
            }
        }

#pragma unroll
        for (int m = 0; m < 32; m++) {
            float a[8];
            *(float4*)&a[0]  = *(const float4*)&As[m][ty * 4];
            *(float4*)&a[4]  = *(const float4*)&As[m][64 + ty * 4];
            float4 b0 = *(const float4*)&Bs[m][tx * 4];
            float4 b1 = *(const float4*)&Bs[m][64 + tx * 4];
            unsigned long long bb4[4];
            bb4[0] = pack2(b0.x, b0.y);
            bb4[1] = pack2(b0.z, b0.w);
            bb4[2] = pack2(b1.x, b1.y);
            bb4[3] = pack2(b1.z, b1.w);
#pragma unroll
            for (int i = 0; i < 8; i++) {
                unsigned long long aa = pack2(a[i], a[i]);
                ffma2(acc2[i][0], aa, bb4[0]);
                ffma2(acc2[i][1], aa, bb4[1]);
                ffma2(acc2[i][2], aa, bb4[2]);
                ffma2(acc2[i][3], aa, bb4[3]);
            }
        }
        __syncthreads();
    }

    float* dst = &g_kvp[(((size_t)(bb * HEADS + hh)) * KV_SPLIT + chunk) * HD * HD];
#pragma unroll
    for (int ih = 0; ih < 2; ih++) {
#pragma unroll
        for (int i2 = 0; i2 < 4; i2++) {
            int i = ih * 4 + i2;
            int d = ih * 64 + ty * 4 + i2;
#pragma unroll
            for (int jh = 0; jh < 2; jh++) {
                float lo0, hi0, lo1, hi1;
                unpack2(acc2[i][jh * 2 + 0], lo0, hi0);
                unpack2(acc2[i][jh * 2 + 1], lo1, hi1);
                float4 o;
                o.x = lo0;
                o.y = hi0;
                o.z = lo1;
                o.w = hi1;
                *(float4*)&dst[d * HD + jh * 64 + tx * 4] = o;
            }
        }
    }
}

__global__ void kvreduce_kernel() {
    int idx = blockIdx.x * 256 + threadIdx.x;
    int bh  = idx >> 14;
    int off = idx & 16383;
    const float* p = &g_kvp[((size_t)bh * KV_SPLIT) * HD * HD + off];
    float s = 0.f;
#pragma unroll
    for (int c = 0; c < KV_SPLIT; c++) s += p[(size_t)c * HD * HD];
    g_kv[idx] = s * (1.f / NPOS);
}

// ============================================================================
// Kernel 6: out = z * (q_rope @ kv)  (register-prefetch pipelined, ffma2)
// ============================================================================
__global__ __launch_bounds__(256) void out_kernel(float* __restrict__ out) {
    const int m0 = blockIdx.x * 128;
    const int hh = blockIdx.y, bb = blockIdx.z;
    __shared__ float Qs[16][132];
    __shared__ float Es[16][132];
    const int tid = threadIdx.x;
    const int tx = tid & 15, ty = tid >> 4;

    unsigned long long acc2[8][4];
#pragma unroll
    for (int i = 0; i < 8; i++)
#pragma unroll
        for (int j = 0; j < 4; j++) acc2[i][j] = 0ull;

    const float* qr = &g_q[((size_t)bb * CHN + 128 * hh) * NPOS];
    const float* kv = &g_kv[((size_t)(bb * HEADS) + hh) * HD * HD];

    const int l_dk0 = tid >> 5,          l_mg0 = (tid & 31) * 4;
    const int l_dk1 = (tid + 256) >> 5,  l_mg1 = ((tid + 256) & 31) * 4;

    float4 pq0, pq1, pe0, pe1;
    pq0 = *(const float4*)&qr[(size_t)(l_dk0) * NPOS + m0 + l_mg0];
    pq1 = *(const float4*)&qr[(size_t)(l_dk1) * NPOS + m0 + l_mg1];
    pe0 = *(const float4*)&kv[(l_dk0) * HD + l_mg0];
    pe1 = *(const float4*)&kv[(l_dk1) * HD + l_mg1];

    for (int d0 = 0; d0 < HD; d0 += 16) {
        *(float4*)&Qs[l_dk0][l_mg0] = pq0;
        *(float4*)&Qs[l_dk1][l_mg1] = pq1;
        *(float4*)&Es[l_dk0][l_mg0] = pe0;
        *(float4*)&Es[l_dk1][l_mg1] = pe1;
        __syncthreads();

        const int d0n = d0 + 16;
        if (d0n < HD) {
            pq0 = *(const float4*)&qr[(size_t)(d0n + l_dk0) * NPOS + m0 + l_mg0];
            pq1 = *(const float4*)&qr[(size_t)(d0n + l_dk1) * NPOS + m0 + l_mg1];
            pe0 = *(const float4*)&kv[(d0n + l_dk0) * HD + l_mg0];
            pe1 = *(const float4*)&kv[(d0n + l_dk1) * HD + l_mg1];
        }

#pragma unroll
        for (int dk = 0; dk < 16; dk++) {
            float ev[8];
            *(float4*)&ev[0] = *(const float4*)&Es[dk][ty * 4];
            *(float4*)&ev[4] = *(const float4*)&Es[dk][64 + ty * 4];
            float4 m0v = *(const float4*)&Qs[dk][tx * 4];
            float4 m1v = *(const float4*)&Qs[dk][64 + tx * 4];
            unsigned long long mm[4];
            mm[0] = pack2(m0v.x, m0v.y);
            mm[1] = pack2(m0v.z, m0v.w);
            mm[2] = pack2(m1v.x, m1v.y);
            mm[3] = pack2(m1v.z, m1v.w);
#pragma unroll
            for (int i = 0; i < 8; i++) {
                unsigned long long ee = pack2(ev[i], ev[i]);
                ffma2(acc2[i][0], ee, mm[0]);
                ffma2(acc2[i][1], ee, mm[1]);
                ffma2(acc2[i][2], ee, mm[2]);
                ffma2(acc2[i][3], ee, mm[3]);
            }
        }
        __syncthreads();
    }

    const float* zb = &g_z[((size_t)bb * HEADS + hh) * NPOS + m0];
#pragma unroll
    for (int ih = 0; ih < 2; ih++) {
#pragma unroll
        for (int i2 = 0; i2 < 4; i2++) {
            int i = ih * 4 + i2;
            int e = ih * 64 + ty * 4 + i2;
            float* dst = out + ((size_t)bb * CHN + 128 * hh + e) * NPOS + m0;
#pragma unroll
            for (int jh = 0; jh < 2; jh++) {
                int mc = jh * 64 + tx * 4;
                float lo0, hi0, lo1, hi1;
                unpack2(acc2[i][jh * 2 + 0], lo0, hi0);
                unpack2(acc2[i][jh * 2 + 1], lo1, hi1);
                float4 o;
                o.x = lo0 * zb[mc + 0];
                o.y = hi0 * zb[mc + 1];
                o.z = lo1 * zb[mc + 2];
                o.w = hi1 * zb[mc + 3];
                *(float4*)&dst[mc] = o;
            }
        }
    }
}

// ============================================================================
// Kernel 7: lepe — depthwise 3x3 conv, out += conv + bias
// ============================================================================
__global__ __launch_bounds__(256) void lepe_kernel(const float* __restrict__ x,
                                                   const float* __restrict__ w,
                                                   const float* __restrict__ bias,
                                                   float* __restrict__ out) {
    const int c = blockIdx.x, bb = blockIdx.y;
    __shared__ float plane[NPOS];
    const float* src = x + ((size_t)bb * CHN + c) * NPOS;
    const int tid = threadIdx.x;
    for (int i = tid; i < NPOS; i += 256) plane[i] = src[i];
    float wv[9];
#pragma unroll
    for (int kk = 0; kk < 9; kk++) wv[kk] = w[c * 9 + kk];
    const float bv = bias[c];
    __syncthreads();

    float* dst = out + ((size_t)bb * CHN + c) * NPOS;
    for (int i = tid; i < NPOS; i += 256) {
        int y = i / IMGW;
        int xx = i - y * IMGW;
        float s = bv;
#pragma unroll
        for (int ky = 0; ky < 3; ky++) {
            int yy = y + ky - 1;
            if (yy < 0 || yy >= IMGW) continue;
#pragma unroll
            for (int kx = 0; kx < 3; kx++) {
                int xs = xx + kx - 1;
                if (xs < 0 || xs >= IMGW) continue;
                s += wv[ky * 3 + kx] * plane[yy * IMGW + xs];
            }
        }
        dst[i] += s;
    }
}

// ============================================================================
extern "C" void kernel_launch(void* const* d_in, const int* in_sizes, int n_in,
                              void* d_out, int out_size) {
    (void)in_sizes; (void)n_in; (void)out_size;
    const float* x    = (const float*)d_in[0];
    const float* Wqk  = (const float*)d_in[1];
    const float* bqk  = (const float*)d_in[2];
    const float* lw   = (const float*)d_in[3];
    const float* lb   = (const float*)d_in[4];
    float* out = (float*)d_out;

    // 1) q,k = elu(W_qk @ x + b) + 1, channels-first
    qk_gemm_kernel<<<dim3(72, 8, BATCH), 256>>>(x, Wqk, bqk);
    // 2) k_mean (raw k)
    colsum_kernel<<<dim3(CHN, BATCH), 256>>>();
    kmean_kernel<<<16, 256>>>();
    // 3) z (raw q)
    z_kernel<<<dim3(9, HEADS, BATCH), 256>>>();
    // 4) RoPE in place
    rope_kernel<<<dim3(NPOS / 256, CHN / 2, BATCH * 2), 256>>>();
    // 5) kv (split-K + deterministic reduce)
    kv_kernel<<<dim3(KV_SPLIT, HEADS, BATCH), 256>>>(x);
    kvreduce_kernel<<<2048, 256>>>();
    // 6) out = z * (q_rope @ kv)
    out_kernel<<<dim3(72, HEADS, BATCH), 256>>>(out);
    // 7) out += depthwise3x3(x) + bias
    lepe_kernel<<<dim3(CHN, BATCH), 256>>>(x, lw, lb, out);
}

// round 12
// speedup vs baseline: 1.4508x; 1.4508x over previous
#include <cuda_runtime.h>
#include <cuda_bf16.h>
#include <math.h>
#include <stdint.h>

#define BATCH   8
#define CHN     512
#define NPOS    9216         // 96*96
#define IMGW    96
#define HEADS   4
#define HD      128
#define QUARTER 2304         // NPOS/4
#define KV_SPLIT 18
#define KV_CHUNK 512         // NPOS / KV_SPLIT

// ---------------- scratch (device globals; no allocation allowed) -------------
__device__ float g_q[BATCH * CHN * NPOS];                       // 151 MB
__device__ float g_k[BATCH * CHN * NPOS];                       // 151 MB
__device__ float g_S[BATCH * HEADS * CHN];
__device__ float g_kmean[BATCH * HEADS * HD];
__device__ float g_z[BATCH * HEADS * NPOS];
__device__ float g_kvp[BATCH * HEADS * KV_SPLIT * HD * HD];     // 37.7 MB
__device__ float g_kv[BATCH * HEADS * HD * HD];

__device__ __forceinline__ float elu1(float v) {
    return v > 0.f ? v + 1.f : expf(v);
}

// ---------------- packed f32x2 helpers (Blackwell sm_103a) --------------------
__device__ __forceinline__ unsigned long long pack2(float lo, float hi) {
    unsigned long long r;
    asm("mov.b64 %0, {%1, %2};" : "=l"(r) : "f"(lo), "f"(hi));
    return r;
}
__device__ __forceinline__ void unpack2(unsigned long long v, float& lo, float& hi) {
    asm("mov.b64 {%0, %1}, %2;" : "=f"(lo), "=f"(hi) : "l"(v));
}
__device__ __forceinline__ void ffma2(unsigned long long& d,
                                      unsigned long long a, unsigned long long b) {
    asm("fma.rn.f32x2 %0, %1, %2, %0;" : "+l"(d) : "l"(a), "l"(b));
}

// ---------------- warp MMA helpers (classic mma.sync — plain sm_80+ PTX) -----
__device__ __forceinline__ uint32_t smem_u32(const void* p) {
    uint32_t a;
    asm("{ .reg .u64 t; cvta.to.shared.u64 t, %1; cvt.u32.u64 %0, t; }" : "=r"(a) : "l"(p));
    return a;
}
__device__ __forceinline__ void ldsm_x4(uint32_t* r, uint32_t addr) {
    asm volatile("ldmatrix.sync.aligned.m8n8.x4.shared.b16 {%0,%1,%2,%3}, [%4];"
        : "=r"(r[0]), "=r"(r[1]), "=r"(r[2]), "=r"(r[3]) : "r"(addr));
}
__device__ __forceinline__ void ldsm_x2(uint32_t* r, uint32_t addr) {
    asm volatile("ldmatrix.sync.aligned.m8n8.x2.shared.b16 {%0,%1}, [%2];"
        : "=r"(r[0]), "=r"(r[1]) : "r"(addr));
}
__device__ __forceinline__ void mma_bf16(float* d, const uint32_t* a, const uint32_t* b) {
    asm volatile(
        "mma.sync.aligned.m16n8k16.row.col.f32.bf16.bf16.f32 "
        "{%0,%1,%2,%3}, {%4,%5,%6,%7}, {%8,%9}, {%0,%1,%2,%3};"
        : "+f"(d[0]), "+f"(d[1]), "+f"(d[2]), "+f"(d[3])
        : "r"(a[0]), "r"(a[1]), "r"(a[2]), "r"(a[3]), "r"(b[0]), "r"(b[1]));
}
__device__ __forceinline__ uint32_t bfpack2(float a, float b) {
    __nv_bfloat16 ha = __float2bfloat16(a), hb = __float2bfloat16(b);
    uint16_t ua = *(uint16_t*)&ha, ub = *(uint16_t*)&hb;
    return (uint32_t)ua | ((uint32_t)ub << 16);
}

#define QK_STRIDE 40   // bf16 elems per smem row (80 B: 16B-aligned, ldmatrix conflict-free)

// ============================================================================
// Kernel 1 (HMMA): qk[b](1024 x 9216) = W_qk @ X[b] via bf16-split mma.sync.
// D = Ahi*Bhi + Ahi*Blo + Alo*Bhi (fp32-class accuracy), fused bias+elu+1.
// CTA 128x128, K=512 in 16 chunks of 32; 8 warps (2 M x 4 N), 64x32 per warp.
// ============================================================================
__global__ __launch_bounds__(256, 2)
void qk_mma_kernel(const float* __restrict__ x,
                   const float* __restrict__ Wqk,
                   const float* __restrict__ bqk) {
    __shared__ __align__(16) __nv_bfloat16 Ah[128][QK_STRIDE];
    __shared__ __align__(16) __nv_bfloat16 Al[128][QK_STRIDE];
    __shared__ __align__(16) __nv_bfloat16 Bh[128][QK_STRIDE];
    __shared__ __align__(16) __nv_bfloat16 Bl[128][QK_STRIDE];

    const int bN = blockIdx.x * 128;
    const int bM = blockIdx.y * 128;
    const int bb = blockIdx.z;
    const float* X = x + (size_t)bb * CHN * NPOS;

    const int tid = threadIdx.x;
    const int wid = tid >> 5, lane = tid & 31;
    const int wm = wid & 1;        // 2 M-groups of 64
    const int wn = wid >> 1;       // 4 N-groups of 32

    float acc[4][4][4];            // [mf][nf][reg]
#pragma unroll
    for (int i = 0; i < 4; i++)
#pragma unroll
        for (int j = 0; j < 4; j++)
#pragma unroll
            for (int r = 0; r < 4; r++) acc[i][j][r] = 0.f;

    const int nb = tid & 127;      // B transpose: n row owned
    const int kg = tid >> 7;       // 0/1: k half

    for (int c = 0; c < 16; c++) {
        const int k0 = c * 32;

        // ---- A tile: W[bM..bM+127][k0..k0+31] -> bf16 hi/lo, [m][k] ----
#pragma unroll
        for (int r = 0; r < 4; r++) {
            int f = tid + r * 256;             // 1024 float4s
            int row = f >> 3, q = f & 7;
            float4 v = *(const float4*)&Wqk[(size_t)(bM + row) * CHN + k0 + q * 4];
            uint32_t h0 = bfpack2(v.x, v.y), h1 = bfpack2(v.z, v.w);
            float rx = v.x - __bfloat162float(__float2bfloat16(v.x));
            float ry = v.y - __bfloat162float(__float2bfloat16(v.y));
            float rz = v.z - __bfloat162float(__float2bfloat16(v.z));
            float rw = v.w - __bfloat162float(__float2bfloat16(v.w));
            *(uint2*)&Ah[row][q * 4] = make_uint2(h0, h1);
            *(uint2*)&Al[row][q * 4] = make_uint2(bfpack2(rx, ry), bfpack2(rz, rw));
        }
        // ---- B tile: X[k][bN+n] -> [n][k] bf16 hi/lo ----
#pragma unroll
        for (int r = 0; r < 4; r++) {
            int kk = kg * 16 + r * 4;
            const float* px = &X[(size_t)(k0 + kk) * NPOS + bN + nb];
            float v0 = px[0], v1 = px[NPOS], v2 = px[2 * NPOS], v3 = px[3 * NPOS];
            float r0 = v0 - __bfloat162float(__float2bfloat16(v0));
            float r1 = v1 - __bfloat162float(__float2bfloat16(v1));
            float r2 = v2 - __bfloat162float(__float2bfloat16(v2));
            float r3 = v3 - __bfloat162float(__float2bfloat16(v3));
            *(uint2*)&Bh[nb][kk] = make_uint2(bfpack2(v0, v1), bfpack2(v2, v3));
            *(uint2*)&Bl[nb][kk] = make_uint2(bfpack2(r0, r1), bfpack2(r2, r3));
        }
        __syncthreads();

#pragma unroll
        for (int ks = 0; ks < 2; ks++) {       // two k16 steps per chunk
            // B fragments (hi & lo) for this warp's 4 n-frags
            uint32_t bh[4][2], bl[4][2];
#pragma unroll
            for (int nf = 0; nf < 4; nf++) {
                int nrow = wn * 32 + nf * 8 + (lane & 7);
                int kcol = ks * 16 + ((lane >> 3) & 1) * 8;
                ldsm_x2(bh[nf], smem_u32(&Bh[nrow][kcol]));
                ldsm_x2(bl[nf], smem_u32(&Bl[nrow][kcol]));
            }
#pragma unroll
            for (int mf = 0; mf < 4; mf++) {
                int mrow = wm * 64 + mf * 16 + (lane & 15);
                int kcol = ks * 16 + (lane >> 4) * 8;
                uint32_t ah[4], al[4];
                ldsm_x4(ah, smem_u32(&Ah[mrow][kcol]));
                ldsm_x4(al, smem_u32(&Al[mrow][kcol]));
#pragma unroll
                for (int nf = 0; nf < 4; nf++) {
                    mma_bf16(acc[mf][nf], ah, bh[nf]);
                    mma_bf16(acc[mf][nf], ah, bl[nf]);
                    mma_bf16(acc[mf][nf], al, bh[nf]);
                }
            }
        }
        __syncthreads();
    }

    // epilogue: bias + elu + 1; acc reg mapping: rows lane/4 (+8), cols (lane%4)*2 (+1)
#pragma unroll
    for (int mf = 0; mf < 4; mf++) {
#pragma unroll
        for (int h = 0; h < 2; h++) {
            int rowg = bM + wm * 64 + mf * 16 + (lane >> 2) + h * 8;
            float bias = bqk[rowg];
            float* dst = (rowg < CHN)
                ? &g_q[((size_t)bb * CHN + rowg) * NPOS]
                : &g_k[((size_t)bb * CHN + (rowg - CHN)) * NPOS];
#pragma unroll
            for (int nf = 0; nf < 4; nf++) {
                int colg = bN + wn * 32 + nf * 8 + (lane & 3) * 2;
                float2 o;
                o.x = elu1(acc[mf][nf][h * 2 + 0] + bias);
                o.y = elu1(acc[mf][nf][h * 2 + 1] + bias);
                *(float2*)&dst[colg] = o;
            }
        }
    }
}

// ============================================================================
// Kernel 2a: per-(b, channel) quarter-n sums of raw k
// ============================================================================
__global__ __launch_bounds__(256) void colsum_kernel() {
    const int c = blockIdx.x, bb = blockIdx.y;
    const float* src = &g_k[((size_t)bb * CHN + c) * NPOS];
    const int tid = threadIdx.x;
    const int q = tid >> 6, l = tid & 63;
    float s = 0.f;
#pragma unroll
    for (int i = 0; i < 36; i++) s += src[q * QUARTER + l + 64 * i];
    __shared__ float red[256];
    red[tid] = s;
    __syncthreads();
#pragma unroll
    for (int off = 32; off >= 1; off >>= 1) {
        if (l < off) red[tid] += red[tid + off];
        __syncthreads();
    }
    if (l == 0) g_S[((size_t)bb * HEADS + q) * CHN + c] = red[tid];
}

__global__ void kmean_kernel() {
    int idx = blockIdx.x * 256 + threadIdx.x;
    if (idx >= BATCH * HEADS * HD) return;
    int d  = idx & 127;
    int hh = (idx >> 7) & 3;
    int bb = idx >> 9;
    const float* S = &g_S[((size_t)bb * HEADS + hh) * CHN];
    g_kmean[idx] = (S[d] + S[128 + d] + S[256 + d] + S[384 + d]) * (1.f / NPOS);
}

// ============================================================================
// Kernel 3: z = 1 / (q_raw . k_mean + eps)
// ============================================================================
__global__ __launch_bounds__(256) void z_kernel() {
    const int chunk = blockIdx.x;
    const int hh = blockIdx.y, bb = blockIdx.z;
    const int tid = threadIdx.x;
    __shared__ float km[HD];
    if (tid < HD) km[tid] = g_kmean[((size_t)bb * HEADS + hh) * HD + tid];
    __syncthreads();
    const int rp = chunk * 256 + tid;
    const float* qbase = g_q + (size_t)bb * CHN * NPOS + (size_t)hh * QUARTER + rp;
    float a0 = 0.f, a1 = 0.f, a2 = 0.f, a3 = 0.f;
#pragma unroll 4
    for (int d = 0; d < HD; d++) {
        float kmv = km[d];
        a0 += qbase[(size_t)(d)       * NPOS] * kmv;
        a1 += qbase[(size_t)(128 + d) * NPOS] * kmv;
        a2 += qbase[(size_t)(256 + d) * NPOS] * kmv;
        a3 += qbase[(size_t)(384 + d) * NPOS] * kmv;
    }
    float* zb = &g_z[((size_t)bb * HEADS + hh) * NPOS + 4 * rp];
    zb[0] = 1.f / (a0 + 1e-6f);
    zb[1] = 1.f / (a1 + 1e-6f);
    zb[2] = 1.f / (a2 + 1e-6f);
    zb[3] = 1.f / (a3 + 1e-6f);
}

// ============================================================================
// Kernel 4: in-place RoPE; angle indexed by COLUMN (pos % 96) per reference broadcast
// ============================================================================
__global__ __launch_bounds__(256) void rope_kernel() {
    const int pos = blockIdx.x * 256 + threadIdx.x;
    const int p = blockIdx.y;
    const int zb = blockIdx.z;
    const int bb = zb >> 1;
    float* buf = (zb & 1) ? g_k : g_q;
    const int col = pos % IMGW;
    float theta = expf((float)p * (-9.210340371976184f / 256.f));
    float ang = (float)col * theta;
    float s, c;
    sincosf(ang, &s, &c);
    size_t base = ((size_t)bb * CHN + 2 * p) * NPOS + pos;
    float re = buf[base];
    float im = buf[base + NPOS];
    buf[base]        = c * re - s * im;
    buf[base + NPOS] = s * re + c * im;
}

// ============================================================================
// Kernel 5: kv partials (split-K, ffma2 microkernel — R8 body)
// ============================================================================
__global__ __launch_bounds__(256) void kv_kernel(const float* __restrict__ x) {
    const int chunk = blockIdx.x;
    const int hh = blockIdx.y, bb = blockIdx.z;
    __shared__ float As[32][132];
    __shared__ float Bs[32][132];
    const int tid = threadIdx.x;
    const int tx = tid & 15, ty = tid >> 4;

    unsigned long long acc2[8][4];
#pragma unroll
    for (int i = 0; i < 8; i++)
#pragma unroll
        for (int j = 0; j < 4; j++) acc2[i][j] = 0ull;

    const float* kr = &g_k[((size_t)bb * CHN + 128 * hh) * NPOS];

    for (int t = 0; t < KV_CHUNK / 32; t++) {
        const int m0 = chunk * KV_CHUNK + t * 32;
        const int posb = hh * QUARTER + (m0 >> 2);
        {
            int g = tid & 7;
            int dbase = tid >> 3;
#pragma unroll
            for (int r = 0; r < 4; r++) {
                int d = dbase + 32 * r;
                float4 v = *(const float4*)&kr[(size_t)d * NPOS + m0 + g * 4];
                As[g * 4 + 0][d] = v.x;
                As[g * 4 + 1][d] = v.y;
                As[g * 4 + 2][d] = v.z;
                As[g * 4 + 3][d] = v.w;
            }
        }
        {
            int rg = tid & 1;
            int j  = (tid >> 1) & 3;
            int ebase = tid >> 3;
#pragma unroll
            for (int r = 0; r < 4; r++) {
                int e = ebase + 32 * r;
                const float* px = x + ((size_t)bb * CHN + 128 * j + e) * NPOS + posb + rg * 4;
                float4 v = *(const float4*)px;
                Bs[(rg * 4 + 0) * 4 + j][e] = v.x;
                Bs[(rg * 4 + 1) * 4 + j][e] = v.y;
                Bs[(rg * 4 + 2) * 4 + j][e] = v.z;
                Bs[(rg * 4 + 3) * 4 + j][e] = v.w;
            }
        }
        __syncthreads();

#pragma unroll
        for (int m = 0; m < 32; m++) {
            float a[8];
            *(float4*)&a[0]  = *(const float4*)&As[m][ty * 4];
            *(float4*)&a[4]  = *(const float4*)&As[m][64 + ty * 4];
            float4 b0 = *(const float4*)&Bs[m][tx * 4];
            float4 b1 = *(const float4*)&Bs[m][64 + tx * 4];
            unsigned long long bb4[4];
            bb4[0] = pack2(b0.x, b0.y);
            bb4[1] = pack2(b0.z, b0.w);
            bb4[2] = pack2(b1.x, b1.y);
            bb4[3] = pack2(b1.z, b1.w);
#pragma unroll
            for (int i = 0; i < 8; i++) {
                unsigned long long aa = pack2(a[i], a[i]);
                ffma2(acc2[i][0], aa, bb4[0]);
                ffma2(acc2[i][1], aa, bb4[1]);
                ffma2(acc2[i][2], aa, bb4[2]);
                ffma2(acc2[i][3], aa, bb4[3]);
            }
        }
        __syncthreads();
    }

    float* dst = &g_kvp[(((size_t)(bb * HEADS + hh)) * KV_SPLIT + chunk) * HD * HD];
#pragma unroll
    for (int ih = 0; ih < 2; ih++) {
#pragma unroll
        for (int i2 = 0; i2 < 4; i2++) {
            int i = ih * 4 + i2;
            int d = ih * 64 + ty * 4 + i2;
#pragma unroll
            for (int jh = 0; jh < 2; jh++) {
                float lo0, hi0, lo1, hi1;
                unpack2(acc2[i][jh * 2 + 0], lo0, hi0);
                unpack2(acc2[i][jh * 2 + 1], lo1, hi1);
                float4 o;
                o.x = lo0;
                o.y = hi0;
                o.z = lo1;
                o.w = hi1;
                *(float4*)&dst[d * HD + jh * 64 + tx * 4] = o;
            }
        }
    }
}

__global__ void kvreduce_kernel() {
    int idx = blockIdx.x * 256 + threadIdx.x;
    int bh  = idx >> 14;
    int off = idx & 16383;
    const float* p = &g_kvp[((size_t)bh * KV_SPLIT) * HD * HD + off];
    float s = 0.f;
#pragma unroll
    for (int c = 0; c < KV_SPLIT; c++) s += p[(size_t)c * HD * HD];
    g_kv[idx] = s * (1.f / NPOS);
}

// ============================================================================
// Kernel 6: out = z * (q_rope @ kv)   (ffma2 microkernel — R8 body)
// ============================================================================
__global__ __launch_bounds__(256) void out_kernel(float* __restrict__ out) {
    const int m0 = blockIdx.x * 128;
    const int hh = blockIdx.y, bb = blockIdx.z;
    __shared__ float Qs[16][132];
    __shared__ float Es[16][132];
    const int tid = threadIdx.x;
    const int tx = tid & 15, ty = tid >> 4;

    unsigned long long acc2[8][4];
#pragma unroll
    for (int i = 0; i < 8; i++)
#pragma unroll
        for (int j = 0; j < 4; j++) acc2[i][j] = 0ull;

    const float* qr = &g_q[((size_t)bb * CHN + 128 * hh) * NPOS];
    const float* kv = &g_kv[((size_t)(bb * HEADS) + hh) * HD * HD];

    for (int d0 = 0; d0 < HD; d0 += 16) {
#pragma unroll
        for (int r = 0; r < 2; r++) {
            int idx = tid + r * 256;
            int dk = idx >> 5;
            int mg = (idx & 31) * 4;
            *(float4*)&Qs[dk][mg] = *(const float4*)&qr[(size_t)(d0 + dk) * NPOS + m0 + mg];
            *(float4*)&Es[dk][mg] = *(const float4*)&kv[(d0 + dk) * HD + mg];
        }
        __syncthreads();
#pragma unroll
        for (int dk = 0; dk < 16; dk++) {
            float ev[8];
            *(float4*)&ev[0] = *(const float4*)&Es[dk][ty * 4];
            *(float4*)&ev[4] = *(const float4*)&Es[dk][64 + ty * 4];
            float4 m0v = *(const float4*)&Qs[dk][tx * 4];
            float4 m1v = *(const float4*)&Qs[dk][64 + tx * 4];
            unsigned long long mm[4];
            mm[0] = pack2(m0v.x, m0v.y);
            mm[1] = pack2(m0v.z, m0v.w);
            mm[2] = pack2(m1v.x, m1v.y);
            mm[3] = pack2(m1v.z, m1v.w);
#pragma unroll
            for (int i = 0; i < 8; i++) {
                unsigned long long ee = pack2(ev[i], ev[i]);
                ffma2(acc2[i][0], ee, mm[0]);
                ffma2(acc2[i][1], ee, mm[1]);
                ffma2(acc2[i][2], ee, mm[2]);
                ffma2(acc2[i][3], ee, mm[3]);
            }
        }
        __syncthreads();
    }

    const float* zb = &g_z[((size_t)bb * HEADS + hh) * NPOS + m0];
#pragma unroll
    for (int ih = 0; ih < 2; ih++) {
#pragma unroll
        for (int i2 = 0; i2 < 4; i2++) {
            int i = ih * 4 + i2;
            int e = ih * 64 + ty * 4 + i2;
            float* dst = out + ((size_t)bb * CHN + 128 * hh + e) * NPOS + m0;
#pragma unroll
            for (int jh = 0; jh < 2; jh++) {
                int mc = jh * 64 + tx * 4;
                float lo0, hi0, lo1, hi1;
                unpack2(acc2[i][jh * 2 + 0], lo0, hi0);
                unpack2(acc2[i][jh * 2 + 1], lo1, hi1);
                float4 o;
                o.x = lo0 * zb[mc + 0];
                o.y = hi0 * zb[mc + 1];
                o.z = lo1 * zb[mc + 2];
                o.w = hi1 * zb[mc + 3];
                *(float4*)&dst[mc] = o;
            }
        }
    }
}

// ============================================================================
// Kernel 7: lepe — depthwise 3x3 conv, out += conv + bias
// ============================================================================
__global__ __launch_bounds__(256) void lepe_kernel(const float* __restrict__ x,
                                                   const float* __restrict__ w,
                                                   const float* __restrict__ bias,
                                                   float* __restrict__ out) {
    const int c = blockIdx.x, bb = blockIdx.y;
    __shared__ float plane[NPOS];
    const float* src = x + ((size_t)bb * CHN + c) * NPOS;
    const int tid = threadIdx.x;
    for (int i = tid; i < NPOS; i += 256) plane[i] = src[i];
    float wv[9];
#pragma unroll
    for (int kk = 0; kk < 9; kk++) wv[kk] = w[c * 9 + kk];
    const float bv = bias[c];
    __syncthreads();

    float* dst = out + ((size_t)bb * CHN + c) * NPOS;
    for (int i = tid; i < NPOS; i += 256) {
        int y = i / IMGW;
        int xx = i - y * IMGW;
        float s = bv;
#pragma unroll
        for (int ky = 0; ky < 3; ky++) {
            int yy = y + ky - 1;
            if (yy < 0 || yy >= IMGW) continue;
#pragma unroll
            for (int kx = 0; kx < 3; kx++) {
                int xs = xx + kx - 1;
                if (xs < 0 || xs >= IMGW) continue;
                s += wv[ky * 3 + kx] * plane[yy * IMGW + xs];
            }
        }
        dst[i] += s;
    }
}

// ============================================================================
extern "C" void kernel_launch(void* const* d_in, const int* in_sizes, int n_in,
                              void* d_out, int out_size) {
    (void)in_sizes; (void)n_in; (void)out_size;
    const float* x    = (const float*)d_in[0];
    const float* Wqk  = (const float*)d_in[1];
    const float* bqk  = (const float*)d_in[2];
    const float* lw   = (const float*)d_in[3];
    const float* lb   = (const float*)d_in[4];
    float* out = (float*)d_out;

    // 1) q,k = elu(W_qk @ x + b) + 1  — bf16-split HMMA (mma.sync)
    qk_mma_kernel<<<dim3(72, 8, BATCH), 256>>>(x, Wqk, bqk);
    // 2) k_mean (raw k)
    colsum_kernel<<<dim3(CHN, BATCH), 256>>>();
    kmean_kernel<<<16, 256>>>();
    // 3) z (raw q)
    z_kernel<<<dim3(9, HEADS, BATCH), 256>>>();
    // 4) RoPE in place
    rope_kernel<<<dim3(NPOS / 256, CHN / 2, BATCH * 2), 256>>>();
    // 5) kv (split-K + deterministic reduce)
    kv_kernel<<<dim3(KV_SPLIT, HEADS, BATCH), 256>>>(x);
    kvreduce_kernel<<<2048, 256>>>();
    // 6) out = z * (q_rope @ kv)
    out_kernel<<<dim3(72, HEADS, BATCH), 256>>>(out);
    // 7) out += depthwise3x3(x) + bias
    lepe_kernel<<<dim3(CHN, BATCH), 256>>>(x, lw, lb, out);
}

// round 13
// speedup vs baseline: 1.5595x; 1.0749x over previous
#include <cuda_runtime.h>
#include <cuda_bf16.h>
#include <math.h>
#include <stdint.h>

#define BATCH   8
#define CHN     512
#define NPOS    9216         // 96*96
#define IMGW    96
#define HEADS   4
#define HD      128
#define QUARTER 2304         // NPOS/4
#define KV_SPLIT 18
#define KV_CHUNK 512         // NPOS / KV_SPLIT
#define LN1E4_256 0.0359779077f   // ln(10000)/256

// ---------------- scratch (device globals; no allocation allowed) -------------
__device__ float g_q[BATCH * CHN * NPOS];                       // raw q (never rope'd)
__device__ float g_k[BATCH * CHN * NPOS];                       // raw k (never rope'd)
__device__ float g_S[BATCH * HEADS * CHN];
__device__ float g_kmean[BATCH * HEADS * HD];
__device__ float g_z[BATCH * HEADS * NPOS];
__device__ float g_kvp[BATCH * HEADS * KV_SPLIT * HD * HD];
__device__ float g_kv[BATCH * HEADS * HD * HD];

__device__ __forceinline__ float elu1(float v) {
    return v > 0.f ? v + 1.f : expf(v);
}

// ---------------- warp MMA helpers (classic mma.sync, verified in R12) --------
__device__ __forceinline__ uint32_t smem_u32(const void* p) {
    uint32_t a;
    asm("{ .reg .u64 t; cvta.to.shared.u64 t, %1; cvt.u32.u64 %0, t; }" : "=r"(a) : "l"(p));
    return a;
}
__device__ __forceinline__ void ldsm_x4(uint32_t* r, uint32_t addr) {
    asm volatile("ldmatrix.sync.aligned.m8n8.x4.shared.b16 {%0,%1,%2,%3}, [%4];"
        : "=r"(r[0]), "=r"(r[1]), "=r"(r[2]), "=r"(r[3]) : "r"(addr));
}
__device__ __forceinline__ void ldsm_x2(uint32_t* r, uint32_t addr) {
    asm volatile("ldmatrix.sync.aligned.m8n8.x2.shared.b16 {%0,%1}, [%2];"
        : "=r"(r[0]), "=r"(r[1]) : "r"(addr));
}
__device__ __forceinline__ void mma_bf16(float* d, const uint32_t* a, const uint32_t* b) {
    asm volatile(
        "mma.sync.aligned.m16n8k16.row.col.f32.bf16.bf16.f32 "
        "{%0,%1,%2,%3}, {%4,%5,%6,%7}, {%8,%9}, {%0,%1,%2,%3};"
        : "+f"(d[0]), "+f"(d[1]), "+f"(d[2]), "+f"(d[3])
        : "r"(a[0]), "r"(a[1]), "r"(a[2]), "r"(a[3]), "r"(b[0]), "r"(b[1]));
}
__device__ __forceinline__ uint32_t bfpack2(float a, float b) {
    __nv_bfloat16 ha = __float2bfloat16(a), hb = __float2bfloat16(b);
    uint16_t ua = *(uint16_t*)&ha, ub = *(uint16_t*)&hb;
    return (uint32_t)ua | ((uint32_t)ub << 16);
}
__device__ __forceinline__ float bfres(float v) {
    return v - __bfloat162float(__float2bfloat16(v));
}

#define QK_STRIDE 40   // bf16 elems per smem row (80 B: 16B-aligned, ldmatrix-friendly)

// ============================================================================
// Kernel 1 (HMMA, R12-verified): qk[b] = W_qk @ X[b], bf16-split, bias+elu+1.
// ============================================================================
__global__ __launch_bounds__(256, 2)
void qk_mma_kernel(const float* __restrict__ x,
                   const float* __restrict__ Wqk,
                   const float* __restrict__ bqk) {
    __shared__ __align__(16) __nv_bfloat16 Ah[128][QK_STRIDE];
    __shared__ __align__(16) __nv_bfloat16 Al[128][QK_STRIDE];
    __shared__ __align__(16) __nv_bfloat16 Bh[128][QK_STRIDE];
    __shared__ __align__(16) __nv_bfloat16 Bl[128][QK_STRIDE];

    const int bN = blockIdx.x * 128;
    const int bM = blockIdx.y * 128;
    const int bb = blockIdx.z;
    const float* X = x + (size_t)bb * CHN * NPOS;

    const int tid = threadIdx.x;
    const int wid = tid >> 5, lane = tid & 31;
    const int wm = wid & 1;
    const int wn = wid >> 1;

    float acc[4][4][4];
#pragma unroll
    for (int i = 0; i < 4; i++)
#pragma unroll
        for (int j = 0; j < 4; j++)
#pragma unroll
            for (int r = 0; r < 4; r++) acc[i][j][r] = 0.f;

    const int nb = tid & 127;
    const int kg = tid >> 7;

    for (int c = 0; c < 16; c++) {
        const int k0 = c * 32;
#pragma unroll
        for (int r = 0; r < 4; r++) {
            int f = tid + r * 256;
            int row = f >> 3, q = f & 7;
            float4 v = *(const float4*)&Wqk[(size_t)(bM + row) * CHN + k0 + q * 4];
            *(uint2*)&Ah[row][q * 4] = make_uint2(bfpack2(v.x, v.y), bfpack2(v.z, v.w));
            *(uint2*)&Al[row][q * 4] = make_uint2(bfpack2(bfres(v.x), bfres(v.y)),
                                                  bfpack2(bfres(v.z), bfres(v.w)));
        }
#pragma unroll
        for (int r = 0; r < 4; r++) {
            int kk = kg * 16 + r * 4;
            const float* px = &X[(size_t)(k0 + kk) * NPOS + bN + nb];
            float v0 = px[0], v1 = px[NPOS], v2 = px[2 * NPOS], v3 = px[3 * NPOS];
            *(uint2*)&Bh[nb][kk] = make_uint2(bfpack2(v0, v1), bfpack2(v2, v3));
            *(uint2*)&Bl[nb][kk] = make_uint2(bfpack2(bfres(v0), bfres(v1)),
                                              bfpack2(bfres(v2), bfres(v3)));
        }
        __syncthreads();

#pragma unroll
        for (int ks = 0; ks < 2; ks++) {
            uint32_t bh[4][2], bl[4][2];
#pragma unroll
            for (int nf = 0; nf < 4; nf++) {
                int nrow = wn * 32 + nf * 8 + (lane & 7);
                int kcol = ks * 16 + ((lane >> 3) & 1) * 8;
                ldsm_x2(bh[nf], smem_u32(&Bh[nrow][kcol]));
                ldsm_x2(bl[nf], smem_u32(&Bl[nrow][kcol]));
            }
#pragma unroll
            for (int mf = 0; mf < 4; mf++) {
                int mrow = wm * 64 + mf * 16 + (lane & 15);
                int kcol = ks * 16 + (lane >> 4) * 8;
                uint32_t ah[4], al[4];
                ldsm_x4(ah, smem_u32(&Ah[mrow][kcol]));
                ldsm_x4(al, smem_u32(&Al[mrow][kcol]));
#pragma unroll
                for (int nf = 0; nf < 4; nf++) {
                    mma_bf16(acc[mf][nf], ah, bh[nf]);
                    mma_bf16(acc[mf][nf], ah, bl[nf]);
                    mma_bf16(acc[mf][nf], al, bh[nf]);
                }
            }
        }
        __syncthreads();
    }

#pragma unroll
    for (int mf = 0; mf < 4; mf++) {
#pragma unroll
        for (int h = 0; h < 2; h++) {
            int rowg = bM + wm * 64 + mf * 16 + (lane >> 2) + h * 8;
            float bias = bqk[rowg];
            float* dst = (rowg < CHN)
                ? &g_q[((size_t)bb * CHN + rowg) * NPOS]
                : &g_k[((size_t)bb * CHN + (rowg - CHN)) * NPOS];
#pragma unroll
            for (int nf = 0; nf < 4; nf++) {
                int colg = bN + wn * 32 + nf * 8 + (lane & 3) * 2;
                float2 o;
                o.x = elu1(acc[mf][nf][h * 2 + 0] + bias);
                o.y = elu1(acc[mf][nf][h * 2 + 1] + bias);
                *(float2*)&dst[colg] = o;
            }
        }
    }
}

// ============================================================================
// Kernel 2a/2b: k_mean from raw k
// ============================================================================
__global__ __launch_bounds__(256) void colsum_kernel() {
    const int c = blockIdx.x, bb = blockIdx.y;
    const float* src = &g_k[((size_t)bb * CHN + c) * NPOS];
    const int tid = threadIdx.x;
    const int q = tid >> 6, l = tid & 63;
    float s = 0.f;
#pragma unroll
    for (int i = 0; i < 36; i++) s += src[q * QUARTER + l + 64 * i];
    __shared__ float red[256];
    red[tid] = s;
    __syncthreads();
#pragma unroll
    for (int off = 32; off >= 1; off >>= 1) {
        if (l < off) red[tid] += red[tid + off];
        __syncthreads();
    }
    if (l == 0) g_S[((size_t)bb * HEADS + q) * CHN + c] = red[tid];
}

__global__ void kmean_kernel() {
    int idx = blockIdx.x * 256 + threadIdx.x;
    if (idx >= BATCH * HEADS * HD) return;
    int d  = idx & 127;
    int hh = (idx >> 7) & 3;
    int bb = idx >> 9;
    const float* S = &g_S[((size_t)bb * HEADS + hh) * CHN];
    g_kmean[idx] = (S[d] + S[128 + d] + S[256 + d] + S[384 + d]) * (1.f / NPOS);
}

// ============================================================================
// Kernel 3: z = 1 / (q_raw . k_mean + eps)
// ============================================================================
__global__ __launch_bounds__(256) void z_kernel() {
    const int chunk = blockIdx.x;
    const int hh = blockIdx.y, bb = blockIdx.z;
    const int tid = threadIdx.x;
    __shared__ float km[HD];
    if (tid < HD) km[tid] = g_kmean[((size_t)bb * HEADS + hh) * HD + tid];
    __syncthreads();
    const int rp = chunk * 256 + tid;
    const float* qbase = g_q + (size_t)bb * CHN * NPOS + (size_t)hh * QUARTER + rp;
    float a0 = 0.f, a1 = 0.f, a2 = 0.f, a3 = 0.f;
#pragma unroll 4
    for (int d = 0; d < HD; d++) {
        float kmv = km[d];
        a0 += qbase[(size_t)(d)       * NPOS] * kmv;
        a1 += qbase[(size_t)(128 + d) * NPOS] * kmv;
        a2 += qbase[(size_t)(256 + d) * NPOS] * kmv;
        a3 += qbase[(size_t)(384 + d) * NPOS] * kmv;
    }
    float* zb = &g_z[((size_t)bb * HEADS + hh) * NPOS + 4 * rp];
    zb[0] = 1.f / (a0 + 1e-6f);
    zb[1] = 1.f / (a1 + 1e-6f);
    zb[2] = 1.f / (a2 + 1e-6f);
    zb[3] = 1.f / (a3 + 1e-6f);
}

// ============================================================================
// Kernel 4 (HMMA + fused RoPE): kv partials.
//   kv[d][e] = sum_m rope(k)[128hh+d][m] * x[128*(m%4)+e][hh*2304+m/4]
// M=d, N=e, K=m (16 tiles of 32 per split chunk).  g_k stays RAW.
// ============================================================================
__global__ __launch_bounds__(256, 2)
void kv_hmma_kernel(const float* __restrict__ x) {
    __shared__ __align__(16) __nv_bfloat16 Ah[128][QK_STRIDE];
    __shared__ __align__(16) __nv_bfloat16 Al[128][QK_STRIDE];
    __shared__ __align__(16) __nv_bfloat16 Bh[128][QK_STRIDE];
    __shared__ __align__(16) __nv_bfloat16 Bl[128][QK_STRIDE];

    const int chunk = blockIdx.x;
    const int hh = blockIdx.y, bb = blockIdx.z;
    const int tid = threadIdx.x;
    const int wid = tid >> 5, lane = tid & 31;
    const int wm = wid & 1, wn = wid >> 1;

    float acc[4][4][4];
#pragma unroll
    for (int i = 0; i < 4; i++)
#pragma unroll
        for (int j = 0; j < 4; j++)
#pragma unroll
            for (int r = 0; r < 4; r++) acc[i][j][r] = 0.f;

    const float* kr = &g_k[((size_t)bb * CHN + 128 * hh) * NPOS];

    // per-thread rope constants (pd fixed across tiles): items r=0,1
    float th[2], ctb[2], stb[2];
#pragma unroll
    for (int r = 0; r < 2; r++) {
        int pd = (tid + r * 256) >> 3;            // 0..63 within head
        float p = (float)(64 * hh + pd);
        th[r] = expf(p * -LN1E4_256);
        sincosf(th[r], &stb[r], &ctb[r]);
    }

    for (int t = 0; t < 16; t++) {
        const int m0 = chunk * KV_CHUNK + t * 32;

        // ---- A staging: k rows with rope (pairs 2pd, 2pd+1) ----
#pragma unroll
        for (int r = 0; r < 2; r++) {
            int item = tid + r * 256;
            int pd = item >> 3, g = item & 7;
            const float* pre = &kr[(size_t)(2 * pd) * NPOS + m0 + 4 * g];
            float4 re4 = *(const float4*)pre;
            float4 im4 = *(const float4*)(pre + NPOS);
            float rev[4] = {re4.x, re4.y, re4.z, re4.w};
            float imv[4] = {im4.x, im4.y, im4.z, im4.w};
            int col0 = (m0 + 4 * g) % IMGW;
            float s, c;
            sincosf((float)col0 * th[r], &s, &c);
            float ore[4], oim[4];
#pragma unroll
            for (int i = 0; i < 4; i++) {
                ore[i] = c * rev[i] - s * imv[i];
                oim[i] = s * rev[i] + c * imv[i];
                float cn = c * ctb[r] - s * stb[r];
                s = s * ctb[r] + c * stb[r];
                c = cn;
            }
            *(uint2*)&Ah[2 * pd][4 * g]     = make_uint2(bfpack2(ore[0], ore[1]), bfpack2(ore[2], ore[3]));
            *(uint2*)&Ah[2 * pd + 1][4 * g] = make_uint2(bfpack2(oim[0], oim[1]), bfpack2(oim[2], oim[3]));
            *(uint2*)&Al[2 * pd][4 * g]     = make_uint2(bfpack2(bfres(ore[0]), bfres(ore[1])),
                                                          bfpack2(bfres(ore[2]), bfres(ore[3])));
            *(uint2*)&Al[2 * pd + 1][4 * g] = make_uint2(bfpack2(bfres(oim[0]), bfres(oim[1])),
                                                          bfpack2(bfres(oim[2]), bfres(oim[3])));
        }
        // ---- B staging: v channels -> Bs[e][m_local] ----
        {
            const int posb = hh * QUARTER + (m0 >> 2);
            int rg = tid & 1, j = (tid >> 1) & 3, ebase = tid >> 3;
#pragma unroll
            for (int r = 0; r < 4; r++) {
                int e = ebase + 32 * r;
                float4 v = *(const float4*)(x + ((size_t)bb * CHN + 128 * j + e) * NPOS + posb + rg * 4);
                float vv[4] = {v.x, v.y, v.z, v.w};
#pragma unroll
                for (int u = 0; u < 4; u++) {
                    int ml = 4 * (rg * 4 + u) + j;
                    __nv_bfloat16 h = __float2bfloat16(vv[u]);
                    Bh[e][ml] = h;
                    Bl[e][ml] = __float2bfloat16(vv[u] - __bfloat162float(h));
                }
            }
        }
        __syncthreads();

#pragma unroll
        for (int ks = 0; ks < 2; ks++) {
            uint32_t bh[4][2], bl[4][2];
#pragma unroll
            for (int nf = 0; nf < 4; nf++) {
                int nrow = wn * 32 + nf * 8 + (lane & 7);
                int kcol = ks * 16 + ((lane >> 3) & 1) * 8;
                ldsm_x2(bh[nf], smem_u32(&Bh[nrow][kcol]));
                ldsm_x2(bl[nf], smem_u32(&Bl[nrow][kcol]));
            }
#pragma unroll
            for (int mf = 0; mf < 4; mf++) {
                int mrow = wm * 64 + mf * 16 + (lane & 15);
                int kcol = ks * 16 + (lane >> 4) * 8;
                uint32_t ah[4], al[4];
                ldsm_x4(ah, smem_u32(&Ah[mrow][kcol]));
                ldsm_x4(al, smem_u32(&Al[mrow][kcol]));
#pragma unroll
                for (int nf = 0; nf < 4; nf++) {
                    mma_bf16(acc[mf][nf], ah, bh[nf]);
                    mma_bf16(acc[mf][nf], ah, bl[nf]);
                    mma_bf16(acc[mf][nf], al, bh[nf]);
                }
            }
        }
        __syncthreads();
    }

    float* dst = &g_kvp[(((size_t)(bb * HEADS + hh)) * KV_SPLIT + chunk) * HD * HD];
#pragma unroll
    for (int mf = 0; mf < 4; mf++) {
#pragma unroll
        for (int h = 0; h < 2; h++) {
            int d = wm * 64 + mf * 16 + (lane >> 2) + h * 8;
#pragma unroll
            for (int nf = 0; nf < 4; nf++) {
                int e = wn * 32 + nf * 8 + (lane & 3) * 2;
                *(float2*)&dst[d * HD + e] =
                    make_float2(acc[mf][nf][h * 2 + 0], acc[mf][nf][h * 2 + 1]);
            }
        }
    }
}

__global__ void kvreduce_kernel() {
    int idx = blockIdx.x * 256 + threadIdx.x;
    int bh  = idx >> 14;
    int off = idx & 16383;
    const float* p = &g_kvp[((size_t)bh * KV_SPLIT) * HD * HD + off];
    float s = 0.f;
#pragma unroll
    for (int c = 0; c < KV_SPLIT; c++) s += p[(size_t)c * HD * HD];
    g_kv[idx] = s * (1.f / NPOS);
}

// ============================================================================
// Kernel 6 (HMMA + fused RoPE): out[128hh+e][m] = z[m] * sum_d rope(q)[d][m]*kv[d][e]
// M=e, N=m (tile 128), K=d (4 chunks of 32).  g_q stays RAW.
// ============================================================================
__global__ __launch_bounds__(256, 2)
void out_hmma_kernel(float* __restrict__ out) {
    __shared__ __align__(16) __nv_bfloat16 Ah[128][QK_STRIDE];
    __shared__ __align__(16) __nv_bfloat16 Al[128][QK_STRIDE];
    __shared__ __align__(16) __nv_bfloat16 Bh[128][QK_STRIDE];
    __shared__ __align__(16) __nv_bfloat16 Bl[128][QK_STRIDE];

    const int m0 = blockIdx.x * 128;
    const int hh = blockIdx.y, bb = blockIdx.z;
    const int tid = threadIdx.x;
    const int wid = tid >> 5, lane = tid & 31;
    const int wm = wid & 1, wn = wid >> 1;

    float acc[4][4][4];
#pragma unroll
    for (int i = 0; i < 4; i++)
#pragma unroll
        for (int j = 0; j < 4; j++)
#pragma unroll
            for (int r = 0; r < 4; r++) acc[i][j][r] = 0.f;

    const float* qr  = &g_q[((size_t)bb * CHN + 128 * hh) * NPOS];
    const float* kvm = &g_kv[((size_t)(bb * HEADS) + hh) * HD * HD];

    for (int dc = 0; dc < 4; dc++) {
        const int d0 = dc * 32;

        // ---- A staging: kv[d][e] -> As[e][dk] (transpose) ----
#pragma unroll
        for (int r = 0; r < 4; r++) {
            int item = tid + r * 256;          // 1024 items
            int dk = item >> 5, eg = item & 31;
            float4 v = *(const float4*)&kvm[(d0 + dk) * HD + 4 * eg];
            float vv[4] = {v.x, v.y, v.z, v.w};
#pragma unroll
            for (int i = 0; i < 4; i++) {
                int e = 4 * eg + i;
                __nv_bfloat16 h = __float2bfloat16(vv[i]);
                Ah[e][dk] = h;
                Al[e][dk] = __float2bfloat16(vv[i] - __bfloat162float(h));
            }
        }
        // ---- B staging: rope(q)[d0+dk][m] -> Bs[m][dk] (transpose, pairs) ----
#pragma unroll
        for (int r = 0; r < 2; r++) {
            int item = tid + r * 256;          // 512 items
            int u = item >> 5, g = item & 31;  // u: pair in chunk, g: m-group
            const float* pre = &qr[(size_t)(d0 + 2 * u) * NPOS + m0 + 4 * g];
            float4 re4 = *(const float4*)pre;
            float4 im4 = *(const float4*)(pre + NPOS);
            float rev[4] = {re4.x, re4.y, re4.z, re4.w};
            float imv[4] = {im4.x, im4.y, im4.z, im4.w};
            float p = (float)(64 * hh + (d0 >> 1) + u);
            float theta = expf(p * -LN1E4_256);
            float ct, st;
            sincosf(theta, &st, &ct);
            int col0 = (m0 + 4 * g) % IMGW;
            float s, c;
            sincosf((float)col0 * theta, &s, &c);
#pragma unroll
            for (int i = 0; i < 4; i++) {
                float ore = c * rev[i] - s * imv[i];
                float oim = s * rev[i] + c * imv[i];
                int m = 4 * g + i;
                __nv_bfloat16 hr = __float2bfloat16(ore);
                __nv_bfloat16 hi = __float2bfloat16(oim);
                Bh[m][2 * u]     = hr;
                Bh[m][2 * u + 1] = hi;
                Bl[m][2 * u]     = __float2bfloat16(ore - __bfloat162float(hr));
                Bl[m][2 * u + 1] = __float2bfloat16(oim - __bfloat162float(hi));
                float cn = c * ct - s * st;
                s = s * ct + c * st;
                c = cn;
            }
        }
        __syncthreads();

#pragma unroll
        for (int ks = 0; ks < 2; ks++) {
            uint32_t bh[4][2], bl[4][2];
#pragma unroll
            for (int nf = 0; nf < 4; nf++) {
                int nrow = wn * 32 + nf * 8 + (lane & 7);
                int kcol = ks * 16 + ((lane >> 3) & 1) * 8;
                ldsm_x2(bh[nf], smem_u32(&Bh[nrow][kcol]));
                ldsm_x2(bl[nf], smem_u32(&Bl[nrow][kcol]));
            }
#pragma unroll
            for (int mf = 0; mf < 4; mf++) {
                int mrow = wm * 64 + mf * 16 + (lane & 15);
                int kcol = ks * 16 + (lane >> 4) * 8;
                uint32_t ah[4], al[4];
                ldsm_x4(ah, smem_u32(&Ah[mrow][kcol]));
                ldsm_x4(al, smem_u32(&Al[mrow][kcol]));
#pragma unroll
                for (int nf = 0; nf < 4; nf++) {
                    mma_bf16(acc[mf][nf], ah, bh[nf]);
                    mma_bf16(acc[mf][nf], ah, bl[nf]);
                    mma_bf16(acc[mf][nf], al, bh[nf]);
                }
            }
        }
        __syncthreads();
    }

    const float* zb = &g_z[((size_t)bb * HEADS + hh) * NPOS + m0];
#pragma unroll
    for (int mf = 0; mf < 4; mf++) {
#pragma unroll
        for (int h = 0; h < 2; h++) {
            int e = wm * 64 + mf * 16 + (lane >> 2) + h * 8;
            float* dst = out + ((size_t)bb * CHN + 128 * hh + e) * NPOS + m0;
#pragma unroll
            for (int nf = 0; nf < 4; nf++) {
                int ml = wn * 32 + nf * 8 + (lane & 3) * 2;
                float2 o;
                o.x = acc[mf][nf][h * 2 + 0] * zb[ml + 0];
                o.y = acc[mf][nf][h * 2 + 1] * zb[ml + 1];
                *(float2*)&dst[ml] = o;
            }
        }
    }
}

// ============================================================================
// Kernel 7: lepe — depthwise 3x3 conv, out += conv + bias
// ============================================================================
__global__ __launch_bounds__(256) void lepe_kernel(const float* __restrict__ x,
                                                   const float* __restrict__ w,
                                                   const float* __restrict__ bias,
                                                   float* __restrict__ out) {
    const int c = blockIdx.x, bb = blockIdx.y;
    __shared__ float plane[NPOS];
    const float* src = x + ((size_t)bb * CHN + c) * NPOS;
    const int tid = threadIdx.x;
    for (int i = tid; i < NPOS; i += 256) plane[i] = src[i];
    float wv[9];
#pragma unroll
    for (int kk = 0; kk < 9; kk++) wv[kk] = w[c * 9 + kk];
    const float bv = bias[c];
    __syncthreads();

    float* dst = out + ((size_t)bb * CHN + c) * NPOS;
    for (int i = tid; i < NPOS; i += 256) {
        int y = i / IMGW;
        int xx = i - y * IMGW;
        float s = bv;
#pragma unroll
        for (int ky = 0; ky < 3; ky++) {
            int yy = y + ky - 1;
            if (yy < 0 || yy >= IMGW) continue;
#pragma unroll
            for (int kx = 0; kx < 3; kx++) {
                int xs = xx + kx - 1;
                if (xs < 0 || xs >= IMGW) continue;
                s += wv[ky * 3 + kx] * plane[yy * IMGW + xs];
            }
        }
        dst[i] += s;
    }
}

// ============================================================================
extern "C" void kernel_launch(void* const* d_in, const int* in_sizes, int n_in,
                              void* d_out, int out_size) {
    (void)in_sizes; (void)n_in; (void)out_size;
    const float* x    = (const float*)d_in[0];
    const float* Wqk  = (const float*)d_in[1];
    const float* bqk  = (const float*)d_in[2];
    const float* lw   = (const float*)d_in[3];
    const float* lb   = (const float*)d_in[4];
    float* out = (float*)d_out;

    // 1) q,k = elu(W_qk @ x + b) + 1  (raw, channels-first)
    qk_mma_kernel<<<dim3(72, 8, BATCH), 256>>>(x, Wqk, bqk);
    // 2) k_mean (raw k)
    colsum_kernel<<<dim3(CHN, BATCH), 256>>>();
    kmean_kernel<<<16, 256>>>();
    // 3) z (raw q)
    z_kernel<<<dim3(9, HEADS, BATCH), 256>>>();
    // 4) kv = rope(k) @ v   (HMMA, rope fused into staging; split-K + reduce)
    kv_hmma_kernel<<<dim3(KV_SPLIT, HEADS, BATCH), 256>>>(x);
    kvreduce_kernel<<<2048, 256>>>();
    // 5) out = z * (rope(q) @ kv)   (HMMA, rope fused)
    out_hmma_kernel<<<dim3(72, HEADS, BATCH), 256>>>(out);
    // 6) out += depthwise3x3(x) + bias
    lepe_kernel<<<dim3(CHN, BATCH), 256>>>(x, lw, lb, out);
}

// round 14
// speedup vs baseline: 1.5836x; 1.0155x over previous
#include <cuda_runtime.h>
#include <cuda_bf16.h>
#include <math.h>
#include <stdint.h>

#define BATCH   8
#define CHN     512
#define NPOS    9216         // 96*96
#define IMGW    96
#define HEADS   4
#define HD      128
#define QUARTER 2304         // NPOS/4
#define KV_SPLIT 18
#define KV_CHUNK 512         // NPOS / KV_SPLIT
#define LN1E4_256 0.0359779077f   // ln(10000)/256

// ---------------- scratch (device globals; no allocation allowed) -------------
__device__ float g_q[BATCH * CHN * NPOS];                       // raw q
__device__ float g_k[BATCH * CHN * NPOS];                       // raw k
__device__ float g_Sp[BATCH * CHN * 72];                        // per-CTA column sums of k
__device__ float g_kmean[BATCH * HEADS * HD];
__device__ float g_z[BATCH * HEADS * NPOS];
__device__ float g_kvp[BATCH * HEADS * KV_SPLIT * HD * HD];
__device__ float g_kv[BATCH * HEADS * HD * HD];
__device__ uint4 g_wh4[1024 * 64];                              // W bf16 hi (8 bf16/uint4)
__device__ uint4 g_wl4[1024 * 64];                              // W bf16 lo

__device__ __forceinline__ float elu1(float v) {
    return v > 0.f ? v + 1.f : expf(v);
}

// ---------------- warp MMA helpers (classic mma.sync, verified R12/R13) -------
__device__ __forceinline__ uint32_t smem_u32(const void* p) {
    uint32_t a;
    asm("{ .reg .u64 t; cvta.to.shared.u64 t, %1; cvt.u32.u64 %0, t; }" : "=r"(a) : "l"(p));
    return a;
}
__device__ __forceinline__ void ldsm_x4(uint32_t* r, uint32_t addr) {
    asm volatile("ldmatrix.sync.aligned.m8n8.x4.shared.b16 {%0,%1,%2,%3}, [%4];"
        : "=r"(r[0]), "=r"(r[1]), "=r"(r[2]), "=r"(r[3]) : "r"(addr));
}
__device__ __forceinline__ void ldsm_x2(uint32_t* r, uint32_t addr) {
    asm volatile("ldmatrix.sync.aligned.m8n8.x2.shared.b16 {%0,%1}, [%2];"
        : "=r"(r[0]), "=r"(r[1]) : "r"(addr));
}
__device__ __forceinline__ void mma_bf16(float* d, const uint32_t* a, const uint32_t* b) {
    asm volatile(
        "mma.sync.aligned.m16n8k16.row.col.f32.bf16.bf16.f32 "
        "{%0,%1,%2,%3}, {%4,%5,%6,%7}, {%8,%9}, {%0,%1,%2,%3};"
        : "+f"(d[0]), "+f"(d[1]), "+f"(d[2]), "+f"(d[3])
        : "r"(a[0]), "r"(a[1]), "r"(a[2]), "r"(a[3]), "r"(b[0]), "r"(b[1]));
}
__device__ __forceinline__ uint32_t bfpack2(float a, float b) {
    __nv_bfloat16 ha = __float2bfloat16(a), hb = __float2bfloat16(b);
    uint16_t ua = *(uint16_t*)&ha, ub = *(uint16_t*)&hb;
    return (uint32_t)ua | ((uint32_t)ub << 16);
}
__device__ __forceinline__ float bfres(float v) {
    return v - __bfloat162float(__float2bfloat16(v));
}

#define QK_STRIDE 40   // bf16 elems per smem row (80 B)

// ============================================================================
// Kernel 0: one-time W_qk -> bf16 hi/lo split (packed 8 bf16 per uint4)
// ============================================================================
__global__ void wsplit_kernel(const float* __restrict__ Wqk) {
    int idx = blockIdx.x * 256 + threadIdx.x;      // 65536 items of 8 elems
    if (idx >= 1024 * 64) return;
    const float* src = &Wqk[(size_t)idx * 8];
    float v[8];
#pragma unroll
    for (int i = 0; i < 8; i++) v[i] = src[i];
    uint4 h, l;
    h.x = bfpack2(v[0], v[1]); h.y = bfpack2(v[2], v[3]);
    h.z = bfpack2(v[4], v[5]); h.w = bfpack2(v[6], v[7]);
    l.x = bfpack2(bfres(v[0]), bfres(v[1])); l.y = bfpack2(bfres(v[2]), bfres(v[3]));
    l.z = bfpack2(bfres(v[4]), bfres(v[5])); l.w = bfpack2(bfres(v[6]), bfres(v[7]));
    g_wh4[idx] = h;
    g_wl4[idx] = l;
}

// ============================================================================
// Kernel 1 (HMMA): qk[b] = W_qk @ X[b], bf16-split, bias+elu+1,
// fused per-CTA k column sums -> g_Sp (replaces colsum kernel).
// ============================================================================
__global__ __launch_bounds__(256, 2)
void qk_mma_kernel(const float* __restrict__ x,
                   const float* __restrict__ bqk) {
    __shared__ __align__(16) __nv_bfloat16 Ah[128][QK_STRIDE];
    __shared__ __align__(16) __nv_bfloat16 Al[128][QK_STRIDE];
    __shared__ __align__(16) __nv_bfloat16 Bh[128][QK_STRIDE];
    __shared__ __align__(16) __nv_bfloat16 Bl[128][QK_STRIDE];
    __shared__ float redS[128][4];

    const int bN = blockIdx.x * 128;
    const int bM = blockIdx.y * 128;
    const int bb = blockIdx.z;
    const float* X = x + (size_t)bb * CHN * NPOS;

    const int tid = threadIdx.x;
    const int wid = tid >> 5, lane = tid & 31;
    const int wm = wid & 1;
    const int wn = wid >> 1;

    float acc[4][4][4];
#pragma unroll
    for (int i = 0; i < 4; i++)
#pragma unroll
        for (int j = 0; j < 4; j++)
#pragma unroll
            for (int r = 0; r < 4; r++) acc[i][j][r] = 0.f;

    const int nb = tid & 127;
    const int kg = tid >> 7;

    for (int c = 0; c < 16; c++) {
        const int k0 = c * 32;
        // A tile: precomputed bf16 hi/lo — pure copy (2 items/thread)
#pragma unroll
        for (int r = 0; r < 2; r++) {
            int f = tid + r * 256;          // 512 items
            int row = f >> 2, qg = f & 3;   // 8-elem groups
            int gi = (bM + row) * 64 + c * 4 + qg;
            uint4 h = g_wh4[gi];
            uint4 l = g_wl4[gi];
            *(uint2*)&Ah[row][qg * 8]     = make_uint2(h.x, h.y);
            *(uint2*)&Ah[row][qg * 8 + 4] = make_uint2(h.z, h.w);
            *(uint2*)&Al[row][qg * 8]     = make_uint2(l.x, l.y);
            *(uint2*)&Al[row][qg * 8 + 4] = make_uint2(l.z, l.w);
        }
        // B tile: X[k][bN+n] -> [n][k] bf16 hi/lo
#pragma unroll
        for (int r = 0; r < 4; r++) {
            int kk = kg * 16 + r * 4;
            const float* px = &X[(size_t)(k0 + kk) * NPOS + bN + nb];
            float v0 = px[0], v1 = px[NPOS], v2 = px[2 * NPOS], v3 = px[3 * NPOS];
            *(uint2*)&Bh[nb][kk] = make_uint2(bfpack2(v0, v1), bfpack2(v2, v3));
            *(uint2*)&Bl[nb][kk] = make_uint2(bfpack2(bfres(v0), bfres(v1)),
                                              bfpack2(bfres(v2), bfres(v3)));
        }
        __syncthreads();

#pragma unroll
        for (int ks = 0; ks < 2; ks++) {
            uint32_t bh[4][2], bl[4][2];
#pragma unroll
            for (int nf = 0; nf < 4; nf++) {
                int nrow = wn * 32 + nf * 8 + (lane & 7);
                int kcol = ks * 16 + ((lane >> 3) & 1) * 8;
                ldsm_x2(bh[nf], smem_u32(&Bh[nrow][kcol]));
                ldsm_x2(bl[nf], smem_u32(&Bl[nrow][kcol]));
            }
#pragma unroll
            for (int mf = 0; mf < 4; mf++) {
                int mrow = wm * 64 + mf * 16 + (lane & 15);
                int kcol = ks * 16 + (lane >> 4) * 8;
                uint32_t ah[4], al[4];
                ldsm_x4(ah, smem_u32(&Ah[mrow][kcol]));
                ldsm_x4(al, smem_u32(&Al[mrow][kcol]));
#pragma unroll
                for (int nf = 0; nf < 4; nf++) {
                    mma_bf16(acc[mf][nf], ah, bh[nf]);
                    mma_bf16(acc[mf][nf], ah, bl[nf]);
                    mma_bf16(acc[mf][nf], al, bh[nf]);
                }
            }
        }
        __syncthreads();
    }

    const bool is_k = (blockIdx.y >= 4);
#pragma unroll
    for (int mf = 0; mf < 4; mf++) {
#pragma unroll
        for (int h = 0; h < 2; h++) {
            int rowg = bM + wm * 64 + mf * 16 + (lane >> 2) + h * 8;
            float bias = bqk[rowg];
            float* dst = (rowg < CHN)
                ? &g_q[((size_t)bb * CHN + rowg) * NPOS]
                : &g_k[((size_t)bb * CHN + (rowg - CHN)) * NPOS];
            float rs = 0.f;
#pragma unroll
            for (int nf = 0; nf < 4; nf++) {
                int colg = bN + wn * 32 + nf * 8 + (lane & 3) * 2;
                float2 o;
                o.x = elu1(acc[mf][nf][h * 2 + 0] + bias);
                o.y = elu1(acc[mf][nf][h * 2 + 1] + bias);
                *(float2*)&dst[colg] = o;
                rs += o.x + o.y;
            }
            if (is_k) {          // block-uniform condition; shfl safe
                rs += __shfl_xor_sync(0xffffffffu, rs, 1);
                rs += __shfl_xor_sync(0xffffffffu, rs, 2);
                if ((lane & 3) == 0)
                    redS[wm * 64 + mf * 16 + (lane >> 2) + h * 8][wn] = rs;
            }
        }
    }
    if (is_k) {
        __syncthreads();
        if (tid < 128) {
            float tot = redS[tid][0] + redS[tid][1] + redS[tid][2] + redS[tid][3];
            int kRow = bM - CHN + tid;
            g_Sp[((size_t)bb * CHN + kRow) * 72 + (bN >> 7)] = tot;
        }
    }
}

// ============================================================================
// Kernel 2: k_mean from g_Sp (72 block sums per channel; quarter hh = 18 blocks)
// ============================================================================
__global__ void kmean_kernel() {
    int idx = blockIdx.x * 256 + threadIdx.x;   // 4096
    if (idx >= BATCH * HEADS * HD) return;
    int d  = idx & 127;
    int hh = (idx >> 7) & 3;
    int bb = idx >> 9;
    float s = 0.f;
#pragma unroll
    for (int j = 0; j < 4; j++) {
        const float* p = &g_Sp[((size_t)bb * CHN + 128 * j + d) * 72 + hh * 18];
#pragma unroll
        for (int t = 0; t < 18; t++) s += p[t];
    }
    g_kmean[idx] = s * (1.f / NPOS);
}

// ============================================================================
// Kernel 3: z = 1 / (q_raw . k_mean + eps)
// ============================================================================
__global__ __launch_bounds__(256) void z_kernel() {
    const int chunk = blockIdx.x;
    const int hh = blockIdx.y, bb = blockIdx.z;
    const int tid = threadIdx.x;
    __shared__ float km[HD];
    if (tid < HD) km[tid] = g_kmean[((size_t)bb * HEADS + hh) * HD + tid];
    __syncthreads();
    const int rp = chunk * 256 + tid;
    const float* qbase = g_q + (size_t)bb * CHN * NPOS + (size_t)hh * QUARTER + rp;
    float a0 = 0.f, a1 = 0.f, a2 = 0.f, a3 = 0.f;
#pragma unroll 4
    for (int d = 0; d < HD; d++) {
        float kmv = km[d];
        a0 += qbase[(size_t)(d)       * NPOS] * kmv;
        a1 += qbase[(size_t)(128 + d) * NPOS] * kmv;
        a2 += qbase[(size_t)(256 + d) * NPOS] * kmv;
        a3 += qbase[(size_t)(384 + d) * NPOS] * kmv;
    }
    float* zb = &g_z[((size_t)bb * HEADS + hh) * NPOS + 4 * rp];
    zb[0] = 1.f / (a0 + 1e-6f);
    zb[1] = 1.f / (a1 + 1e-6f);
    zb[2] = 1.f / (a2 + 1e-6f);
    zb[3] = 1.f / (a3 + 1e-6f);
}

// ============================================================================
// Kernel 4 (HMMA + fused RoPE): kv partials (R13-verified body)
// ============================================================================
__global__ __launch_bounds__(256, 2)
void kv_hmma_kernel(const float* __restrict__ x) {
    __shared__ __align__(16) __nv_bfloat16 Ah[128][QK_STRIDE];
    __shared__ __align__(16) __nv_bfloat16 Al[128][QK_STRIDE];
    __shared__ __align__(16) __nv_bfloat16 Bh[128][QK_STRIDE];
    __shared__ __align__(16) __nv_bfloat16 Bl[128][QK_STRIDE];

    const int chunk = blockIdx.x;
    const int hh = blockIdx.y, bb = blockIdx.z;
    const int tid = threadIdx.x;
    const int wid = tid >> 5, lane = tid & 31;
    const int wm = wid & 1, wn = wid >> 1;

    float acc[4][4][4];
#pragma unroll
    for (int i = 0; i < 4; i++)
#pragma unroll
        for (int j = 0; j < 4; j++)
#pragma unroll
            for (int r = 0; r < 4; r++) acc[i][j][r] = 0.f;

    const float* kr = &g_k[((size_t)bb * CHN + 128 * hh) * NPOS];

    float th[2], ctb[2], stb[2];
#pragma unroll
    for (int r = 0; r < 2; r++) {
        int pd = (tid + r * 256) >> 3;
        float p = (float)(64 * hh + pd);
        th[r] = expf(p * -LN1E4_256);
        sincosf(th[r], &stb[r], &ctb[r]);
    }

    for (int t = 0; t < 16; t++) {
        const int m0 = chunk * KV_CHUNK + t * 32;
#pragma unroll
        for (int r = 0; r < 2; r++) {
            int item = tid + r * 256;
            int pd = item >> 3, g = item & 7;
            const float* pre = &kr[(size_t)(2 * pd) * NPOS + m0 + 4 * g];
            float4 re4 = *(const float4*)pre;
            float4 im4 = *(const float4*)(pre + NPOS);
            float rev[4] = {re4.x, re4.y, re4.z, re4.w};
            float imv[4] = {im4.x, im4.y, im4.z, im4.w};
            int col0 = (m0 + 4 * g) % IMGW;
            float s, c;
            sincosf((float)col0 * th[r], &s, &c);
            float ore[4], oim[4];
#pragma unroll
            for (int i = 0; i < 4; i++) {
                ore[i] = c * rev[i] - s * imv[i];
                oim[i] = s * rev[i] + c * imv[i];
                float cn = c * ctb[r] - s * stb[r];
                s = s * ctb[r] + c * stb[r];
                c = cn;
            }
            *(uint2*)&Ah[2 * pd][4 * g]     = make_uint2(bfpack2(ore[0], ore[1]), bfpack2(ore[2], ore[3]));
            *(uint2*)&Ah[2 * pd + 1][4 * g] = make_uint2(bfpack2(oim[0], oim[1]), bfpack2(oim[2], oim[3]));
            *(uint2*)&Al[2 * pd][4 * g]     = make_uint2(bfpack2(bfres(ore[0]), bfres(ore[1])),
                                                          bfpack2(bfres(ore[2]), bfres(ore[3])));
            *(uint2*)&Al[2 * pd + 1][4 * g] = make_uint2(bfpack2(bfres(oim[0]), bfres(oim[1])),
                                                          bfpack2(bfres(oim[2]), bfres(oim[3])));
        }
        {
            const int posb = hh * QUARTER + (m0 >> 2);
            int rg = tid & 1, j = (tid >> 1) & 3, ebase = tid >> 3;
#pragma unroll
            for (int r = 0; r < 4; r++) {
                int e = ebase + 32 * r;
                float4 v = *(const float4*)(x + ((size_t)bb * CHN + 128 * j + e) * NPOS + posb + rg * 4);
                float vv[4] = {v.x, v.y, v.z, v.w};
#pragma unroll
                for (int u = 0; u < 4; u++) {
                    int ml = 4 * (rg * 4 + u) + j;
                    __nv_bfloat16 h = __float2bfloat16(vv[u]);
                    Bh[e][ml] = h;
                    Bl[e][ml] = __float2bfloat16(vv[u] - __bfloat162float(h));
                }
            }
        }
        __syncthreads();

#pragma unroll
        for (int ks = 0; ks < 2; ks++) {
            uint32_t bh[4][2], bl[4][2];
#pragma unroll
            for (int nf = 0; nf < 4; nf++) {
                int nrow = wn * 32 + nf * 8 + (lane & 7);
                int kcol = ks * 16 + ((lane >> 3) & 1) * 8;
                ldsm_x2(bh[nf], smem_u32(&Bh[nrow][kcol]));
                ldsm_x2(bl[nf], smem_u32(&Bl[nrow][kcol]));
            }
#pragma unroll
            for (int mf = 0; mf < 4; mf++) {
                int mrow = wm * 64 + mf * 16 + (lane & 15);
                int kcol = ks * 16 + (lane >> 4) * 8;
                uint32_t ah[4], al[4];
                ldsm_x4(ah, smem_u32(&Ah[mrow][kcol]));
                ldsm_x4(al, smem_u32(&Al[mrow][kcol]));
#pragma unroll
                for (int nf = 0; nf < 4; nf++) {
                    mma_bf16(acc[mf][nf], ah, bh[nf]);
                    mma_bf16(acc[mf][nf], ah, bl[nf]);
                    mma_bf16(acc[mf][nf], al, bh[nf]);
                }
            }
        }
        __syncthreads();
    }

    float* dst = &g_kvp[(((size_t)(bb * HEADS + hh)) * KV_SPLIT + chunk) * HD * HD];
#pragma unroll
    for (int mf = 0; mf < 4; mf++) {
#pragma unroll
        for (int h = 0; h < 2; h++) {
            int d = wm * 64 + mf * 16 + (lane >> 2) + h * 8;
#pragma unroll
            for (int nf = 0; nf < 4; nf++) {
                int e = wn * 32 + nf * 8 + (lane & 3) * 2;
                *(float2*)&dst[d * HD + e] =
                    make_float2(acc[mf][nf][h * 2 + 0], acc[mf][nf][h * 2 + 1]);
            }
        }
    }
}

__global__ void kvreduce_kernel() {
    int idx = blockIdx.x * 256 + threadIdx.x;
    int bh  = idx >> 14;
    int off = idx & 16383;
    const float* p = &g_kvp[((size_t)bh * KV_SPLIT) * HD * HD + off];
    float s = 0.f;
#pragma unroll
    for (int c = 0; c < KV_SPLIT; c++) s += p[(size_t)c * HD * HD];
    g_kv[idx] = s * (1.f / NPOS);
}

// ============================================================================
// Kernel 6 (HMMA + fused RoPE): out (R13-verified body)
// ============================================================================
__global__ __launch_bounds__(256, 2)
void out_hmma_kernel(float* __restrict__ out) {
    __shared__ __align__(16) __nv_bfloat16 Ah[128][QK_STRIDE];
    __shared__ __align__(16) __nv_bfloat16 Al[128][QK_STRIDE];
    __shared__ __align__(16) __nv_bfloat16 Bh[128][QK_STRIDE];
    __shared__ __align__(16) __nv_bfloat16 Bl[128][QK_STRIDE];

    const int m0 = blockIdx.x * 128;
    const int hh = blockIdx.y, bb = blockIdx.z;
    const int tid = threadIdx.x;
    const int wid = tid >> 5, lane = tid & 31;
    const int wm = wid & 1, wn = wid >> 1;

    float acc[4][4][4];
#pragma unroll
    for (int i = 0; i < 4; i++)
#pragma unroll
        for (int j = 0; j < 4; j++)
#pragma unroll
            for (int r = 0; r < 4; r++) acc[i][j][r] = 0.f;

    const float* qr  = &g_q[((size_t)bb * CHN + 128 * hh) * NPOS];
    const float* kvm = &g_kv[((size_t)(bb * HEADS) + hh) * HD * HD];

    for (int dc = 0; dc < 4; dc++) {
        const int d0 = dc * 32;
#pragma unroll
        for (int r = 0; r < 4; r++) {
            int item = tid + r * 256;
            int dk = item >> 5, eg = item & 31;
            float4 v = *(const float4*)&kvm[(d0 + dk) * HD + 4 * eg];
            float vv[4] = {v.x, v.y, v.z, v.w};
#pragma unroll
            for (int i = 0; i < 4; i++) {
                int e = 4 * eg + i;
                __nv_bfloat16 h = __float2bfloat16(vv[i]);
                Ah[e][dk] = h;
                Al[e][dk] = __float2bfloat16(vv[i] - __bfloat162float(h));
            }
        }
#pragma unroll
        for (int r = 0; r < 2; r++) {
            int item = tid + r * 256;
            int u = item >> 5, g = item & 31;
            const float* pre = &qr[(size_t)(d0 + 2 * u) * NPOS + m0 + 4 * g];
            float4 re4 = *(const float4*)pre;
            float4 im4 = *(const float4*)(pre + NPOS);
            float rev[4] = {re4.x, re4.y, re4.z, re4.w};
            float imv[4] = {im4.x, im4.y, im4.z, im4.w};
            float p = (float)(64 * hh + (d0 >> 1) + u);
            float theta = expf(p * -LN1E4_256);
            float ct, st;
            sincosf(theta, &st, &ct);
            int col0 = (m0 + 4 * g) % IMGW;
            float s, c;
            sincosf((float)col0 * theta, &s, &c);
#pragma unroll
            for (int i = 0; i < 4; i++) {
                float ore = c * rev[i] - s * imv[i];
                float oim = s * rev[i] + c * imv[i];
                int m = 4 * g + i;
                __nv_bfloat16 hr = __float2bfloat16(ore);
                __nv_bfloat16 hi = __float2bfloat16(oim);
                Bh[m][2 * u]     = hr;
                Bh[m][2 * u + 1] = hi;
                Bl[m][2 * u]     = __float2bfloat16(ore - __bfloat162float(hr));
                Bl[m][2 * u + 1] = __float2bfloat16(oim - __bfloat162float(hi));
                float cn = c * ct - s * st;
                s = s * ct + c * st;
                c = cn;
            }
        }
        __syncthreads();

#pragma unroll
        for (int ks = 0; ks < 2; ks++) {
            uint32_t bh[4][2], bl[4][2];
#pragma unroll
            for (int nf = 0; nf < 4; nf++) {
                int nrow = wn * 32 + nf * 8 + (lane & 7);
                int kcol = ks * 16 + ((lane >> 3) & 1) * 8;
                ldsm_x2(bh[nf], smem_u32(&Bh[nrow][kcol]));
                ldsm_x2(bl[nf], smem_u32(&Bl[nrow][kcol]));
            }
#pragma unroll
            for (int mf = 0; mf < 4; mf++) {
                int mrow = wm * 64 + mf * 16 + (lane & 15);
                int kcol = ks * 16 + (lane >> 4) * 8;
                uint32_t ah[4], al[4];
                ldsm_x4(ah, smem_u32(&Ah[mrow][kcol]));
                ldsm_x4(al, smem_u32(&Al[mrow][kcol]));
#pragma unroll
                for (int nf = 0; nf < 4; nf++) {
                    mma_bf16(acc[mf][nf], ah, bh[nf]);
                    mma_bf16(acc[mf][nf], ah, bl[nf]);
                    mma_bf16(acc[mf][nf], al, bh[nf]);
                }
            }
        }
        __syncthreads();
    }

    const float* zb = &g_z[((size_t)bb * HEADS + hh) * NPOS + m0];
#pragma unroll
    for (int mf = 0; mf < 4; mf++) {
#pragma unroll
        for (int h = 0; h < 2; h++) {
            int e = wm * 64 + mf * 16 + (lane >> 2) + h * 8;
            float* dst = out + ((size_t)bb * CHN + 128 * hh + e) * NPOS + m0;
#pragma unroll
            for (int nf = 0; nf < 4; nf++) {
                int ml = wn * 32 + nf * 8 + (lane & 3) * 2;
                float2 o;
                o.x = acc[mf][nf][h * 2 + 0] * zb[ml + 0];
                o.y = acc[mf][nf][h * 2 + 1] * zb[ml + 1];
                *(float2*)&dst[ml] = o;
            }
        }
    }
}

// ============================================================================
// Kernel 7: lepe — depthwise 3x3 conv, out += conv + bias
// ============================================================================
__global__ __launch_bounds__(256) void lepe_kernel(const float* __restrict__ x,
                                                   const float* __restrict__ w,
                                                   const float* __restrict__ bias,
                                                   float* __restrict__ out) {
    const int c = blockIdx.x, bb = blockIdx.y;
    __shared__ float plane[NPOS];
    const float* src = x + ((size_t)bb * CHN + c) * NPOS;
    const int tid = threadIdx.x;
    for (int i = tid; i < NPOS; i += 256) plane[i] = src[i];
    float wv[9];
#pragma unroll
    for (int kk = 0; kk < 9; kk++) wv[kk] = w[c * 9 + kk];
    const float bv = bias[c];
    __syncthreads();

    float* dst = out + ((size_t)bb * CHN + c) * NPOS;
    for (int i = tid; i < NPOS; i += 256) {
        int y = i / IMGW;
        int xx = i - y * IMGW;
        float s = bv;
#pragma unroll
        for (int ky = 0; ky < 3; ky++) {
            int yy = y + ky - 1;
            if (yy < 0 || yy >= IMGW) continue;
#pragma unroll
            for (int kx = 0; kx < 3; kx++) {
                int xs = xx + kx - 1;
                if (xs < 0 || xs >= IMGW) continue;
                s += wv[ky * 3 + kx] * plane[yy * IMGW + xs];
            }
        }
        dst[i] += s;
    }
}

// ============================================================================
extern "C" void kernel_launch(void* const* d_in, const int* in_sizes, int n_in,
                              void* d_out, int out_size) {
    (void)in_sizes; (void)n_in; (void)out_size;
    const float* x    = (const float*)d_in[0];
    const float* Wqk  = (const float*)d_in[1];
    const float* bqk  = (const float*)d_in[2];
    const float* lw   = (const float*)d_in[3];
    const float* lb   = (const float*)d_in[4];
    float* out = (float*)d_out;

    // 0) one-time W split (2 MB; negligible)
    wsplit_kernel<<<256, 256>>>(Wqk);
    // 1) q,k = elu(W_qk @ x + b) + 1  + fused k column sums
    qk_mma_kernel<<<dim3(72, 8, BATCH), 256>>>(x, bqk);
    // 2) k_mean from g_Sp
    kmean_kernel<<<16, 256>>>();
    // 3) z (raw q)
    z_kernel<<<dim3(9, HEADS, BATCH), 256>>>();
    // 4) kv = rope(k) @ v  (split-K + reduce)
    kv_hmma_kernel<<<dim3(KV_SPLIT, HEADS, BATCH), 256>>>(x);
    kvreduce_kernel<<<2048, 256>>>();
    // 5) out = z * (rope(q) @ kv)
    out_hmma_kernel<<<dim3(72, HEADS, BATCH), 256>>>(out);
    // 6) out += depthwise3x3(x) + bias
    lepe_kernel<<<dim3(CHN, BATCH), 256>>>(x, lw, lb, out);
}